// round 1
// baseline (speedup 1.0000x reference)
#include <cuda_runtime.h>

#define NBATCH 8
#define NTOK   4096
#define DDIM   256
#define BM     64
#define BN     64
#define QPAD   260   // 256 + 4 pad: bank pattern (4*t + u) -> conflict-free
#define PPAD   68    // 64 + 4 pad

// Scratch for Q, K, V: (8, 4096, 256) fp32 each, token-major.
__device__ float g_q[(size_t)NBATCH * NTOK * DDIM];
__device__ float g_k[(size_t)NBATCH * NTOK * DDIM];
__device__ float g_v[(size_t)NBATCH * NTOK * DDIM];

__device__ __forceinline__ unsigned f2tf32(float f) {
    unsigned u;
    asm("cvt.rna.tf32.f32 %0, %1;" : "=r"(u) : "f"(f));
    return u;
}
__device__ __forceinline__ float tf32f(float f) { return __uint_as_float(f2tf32(f)); }

// m16n8k8 TF32 mma, fp32 accumulate.
// A (16x8 row-major): a0=(g,t) a1=(g+8,t) a2=(g,t+4) a3=(g+8,t+4),  g=lane>>2, t=lane&3
// B (8x8 "col"):      b0=(k=t, n=g) b1=(k=t+4, n=g)
// C (16x8):           c0=(g,2t) c1=(g,2t+1) c2=(g+8,2t) c3=(g+8,2t+1)
__device__ __forceinline__ void mma_tf32(float* c, unsigned a0, unsigned a1, unsigned a2,
                                         unsigned a3, unsigned b0, unsigned b1) {
    asm volatile(
        "mma.sync.aligned.m16n8k8.row.col.f32.tf32.tf32.f32 "
        "{%0,%1,%2,%3},{%4,%5,%6,%7},{%8,%9},{%0,%1,%2,%3};\n"
        : "+f"(c[0]), "+f"(c[1]), "+f"(c[2]), "+f"(c[3])
        : "r"(a0), "r"(a1), "r"(a2), "r"(a3), "r"(b0), "r"(b1));
}

// ============================================================================
// Kernel 1: QKV projection.
// out[b][n][d] = sum_c x[b][c][n] * W[d][c]
// CTA tile: 128 tokens x 64 d-cols, K-chunk 32. 8 warps, each: 16 rows x 64 cols.
// grid: (32 token-tiles, 12 = 3 mats * 4 d-tiles, 8 batches)
// ============================================================================
__global__ __launch_bounds__(256) void qkv_proj_kernel(
    const float* __restrict__ x, const float* __restrict__ Wq,
    const float* __restrict__ Wk, const float* __restrict__ Wv)
{
    __shared__ float Xs[32][132];  // [k][m], pad 132: banks (4t+g) distinct
    __shared__ float Ws[64][36];   // [d][k], pad 36:  banks (4g+t) distinct

    const int batch = blockIdx.z;
    const int n0    = blockIdx.x * 128;
    const int mat   = blockIdx.y >> 2;
    const int d0    = (blockIdx.y & 3) * 64;
    const float* W  = (mat == 0) ? Wq : ((mat == 1) ? Wk : Wv);
    float* outg     = (mat == 0) ? g_q : ((mat == 1) ? g_k : g_v);

    const int tid = threadIdx.x, warp = tid >> 5, lane = tid & 31;
    const int g = lane >> 2, t = lane & 3;
    const int m0 = warp * 16;

    float acc[8][4];
#pragma unroll
    for (int nf = 0; nf < 8; nf++)
#pragma unroll
        for (int i = 0; i < 4; i++) acc[nf][i] = 0.f;

    for (int kc = 0; kc < 256; kc += 32) {
        // X tile: rows c = kc..kc+31, cols n = n0..n0+127 (contiguous in n)
#pragma unroll
        for (int i = tid; i < 1024; i += 256) {
            int r = i >> 5, cq = i & 31;
            float4 v = *(const float4*)(x + ((size_t)(batch * 256 + kc + r)) * 4096 + n0 + cq * 4);
            float* d = &Xs[r][cq * 4];
            d[0] = tf32f(v.x); d[1] = tf32f(v.y); d[2] = tf32f(v.z); d[3] = tf32f(v.w);
        }
        // W tile: rows d0..d0+63, cols kc..kc+31
#pragma unroll
        for (int i = tid; i < 512; i += 256) {
            int r = i >> 3, cq = i & 7;
            float4 v = *(const float4*)(W + (size_t)(d0 + r) * 256 + kc + cq * 4);
            float* d = &Ws[r][cq * 4];
            d[0] = tf32f(v.x); d[1] = tf32f(v.y); d[2] = tf32f(v.z); d[3] = tf32f(v.w);
        }
        __syncthreads();

#pragma unroll
        for (int k8 = 0; k8 < 32; k8 += 8) {
            unsigned a0 = __float_as_uint(Xs[k8 + t][m0 + g]);
            unsigned a1 = __float_as_uint(Xs[k8 + t][m0 + 8 + g]);
            unsigned a2 = __float_as_uint(Xs[k8 + t + 4][m0 + g]);
            unsigned a3 = __float_as_uint(Xs[k8 + t + 4][m0 + 8 + g]);
#pragma unroll
            for (int nf = 0; nf < 8; nf++) {
                unsigned b0 = __float_as_uint(Ws[nf * 8 + g][k8 + t]);
                unsigned b1 = __float_as_uint(Ws[nf * 8 + g][k8 + t + 4]);
                mma_tf32(acc[nf], a0, a1, a2, a3, b0, b1);
            }
        }
        __syncthreads();
    }

    // Write (b, token, d) row-major
    float* ob = outg + ((size_t)batch * NTOK + n0 + m0) * DDIM + d0;
#pragma unroll
    for (int nf = 0; nf < 8; nf++) {
        int d = nf * 8 + 2 * t;
        *(float2*)(ob + (size_t)g * DDIM + d)       = make_float2(acc[nf][0], acc[nf][1]);
        *(float2*)(ob + (size_t)(g + 8) * DDIM + d) = make_float2(acc[nf][2], acc[nf][3]);
    }
}

// ============================================================================
// Kernel 2: flash attention over N=4096, D=256, scale 1/16.
// CTA: 64 queries, loop 64-key tiles. 8 warps / 256 threads.
//   S phase: warps 4(m) x 2(n), each 16x32 of the 64x64 S tile.
//   PV phase: warps own 32 d-columns each, all 64 rows -> 64 accum regs/thread.
// grid: (64 query tiles, 8 batches)
// ============================================================================
__global__ __launch_bounds__(256) void attn_kernel(float* __restrict__ out)
{
    extern __shared__ float smf[];
    float* Qs    = smf;                  // 64 * 260
    float* Ks    = Qs + BM * QPAD;       // 64 * 260
    float* Vs    = Ks + BN * QPAD;       // 64 * 260
    float* Ps    = Vs + BN * QPAD;       // 64 * 68  (raw S, then P)
    float* row_m = Ps + BM * PPAD;       // 64
    float* row_l = row_m + BM;           // 64
    float* row_c = row_l + BM;           // 64

    const int batch = blockIdx.y;
    const int m0g   = blockIdx.x * BM;
    const int tid = threadIdx.x, warp = tid >> 5, lane = tid & 31;
    const int g = lane >> 2, t = lane & 3;
    const int wm = warp >> 1, wn = warp & 1;   // S-phase partition
    const int dw = warp * 32;                  // PV-phase d slice

    // Load Q tile once (TF32-rounded)
    const float* Qg = g_q + ((size_t)batch * NTOK + m0g) * DDIM;
#pragma unroll
    for (int i = tid; i < BM * DDIM / 4; i += 256) {
        int r = i >> 6, cq = i & 63;
        float4 v = *(const float4*)(Qg + (size_t)r * DDIM + cq * 4);
        float* d = Qs + r * QPAD + cq * 4;
        d[0] = tf32f(v.x); d[1] = tf32f(v.y); d[2] = tf32f(v.z); d[3] = tf32f(v.w);
    }
    if (tid < BM) { row_m[tid] = -1e30f; row_l[tid] = 0.f; }

    float o[4][4][4];
#pragma unroll
    for (int mt = 0; mt < 4; mt++)
#pragma unroll
        for (int nf = 0; nf < 4; nf++)
#pragma unroll
            for (int i = 0; i < 4; i++) o[mt][nf][i] = 0.f;

    for (int j = 0; j < NTOK / BN; j++) {
        // ---- load K_j, V_j ----
        const float* Kg = g_k + ((size_t)batch * NTOK + j * BN) * DDIM;
        const float* Vg = g_v + ((size_t)batch * NTOK + j * BN) * DDIM;
#pragma unroll
        for (int i = tid; i < BN * DDIM / 4; i += 256) {
            int r = i >> 6, cq = i & 63;
            float4 kv = *(const float4*)(Kg + (size_t)r * DDIM + cq * 4);
            float4 vv = *(const float4*)(Vg + (size_t)r * DDIM + cq * 4);
            float* kd = Ks + r * QPAD + cq * 4;
            kd[0] = tf32f(kv.x); kd[1] = tf32f(kv.y); kd[2] = tf32f(kv.z); kd[3] = tf32f(kv.w);
            float* vd = Vs + r * QPAD + cq * 4;
            vd[0] = tf32f(vv.x); vd[1] = tf32f(vv.y); vd[2] = tf32f(vv.z); vd[3] = tf32f(vv.w);
        }
        __syncthreads();

        // ---- S = Q K^T ----
        float s[4][4];
#pragma unroll
        for (int nf = 0; nf < 4; nf++)
#pragma unroll
            for (int i = 0; i < 4; i++) s[nf][i] = 0.f;

#pragma unroll
        for (int k0 = 0; k0 < DDIM; k0 += 8) {
            const float* qrow = Qs + wm * 16 * QPAD + k0;
            unsigned a0 = __float_as_uint(qrow[g * QPAD + t]);
            unsigned a1 = __float_as_uint(qrow[(g + 8) * QPAD + t]);
            unsigned a2 = __float_as_uint(qrow[g * QPAD + t + 4]);
            unsigned a3 = __float_as_uint(qrow[(g + 8) * QPAD + t + 4]);
#pragma unroll
            for (int nf = 0; nf < 4; nf++) {
                const float* krow = Ks + (wn * 32 + nf * 8) * QPAD + k0;
                unsigned b0 = __float_as_uint(krow[g * QPAD + t]);
                unsigned b1 = __float_as_uint(krow[g * QPAD + t + 4]);
                mma_tf32(s[nf], a0, a1, a2, a3, b0, b1);
            }
        }
        // store scaled S
#pragma unroll
        for (int nf = 0; nf < 4; nf++) {
            int col = wn * 32 + nf * 8 + 2 * t;
            int r = wm * 16 + g;
            Ps[r * PPAD + col]           = s[nf][0] * 0.0625f;
            Ps[r * PPAD + col + 1]       = s[nf][1] * 0.0625f;
            Ps[(r + 8) * PPAD + col]     = s[nf][2] * 0.0625f;
            Ps[(r + 8) * PPAD + col + 1] = s[nf][3] * 0.0625f;
        }
        __syncthreads();

        // ---- online softmax: warp w owns rows w*8..w*8+7; 4 lanes/row ----
        {
            int row = warp * 8 + g;
            int c0 = t * 16;
            float mx = -1e30f;
#pragma unroll
            for (int c = 0; c < 16; c++) mx = fmaxf(mx, Ps[row * PPAD + c0 + c]);
            mx = fmaxf(mx, __shfl_xor_sync(0xffffffffu, mx, 1));
            mx = fmaxf(mx, __shfl_xor_sync(0xffffffffu, mx, 2));
            float mold = row_m[row];
            float mnew = fmaxf(mold, mx);
            float sum = 0.f;
#pragma unroll
            for (int c = 0; c < 16; c++) {
                float p = __expf(Ps[row * PPAD + c0 + c] - mnew);
                Ps[row * PPAD + c0 + c] = tf32f(p);
                sum += p;
            }
            sum += __shfl_xor_sync(0xffffffffu, sum, 1);
            sum += __shfl_xor_sync(0xffffffffu, sum, 2);
            if (t == 0) {
                float corr = __expf(mold - mnew);
                row_c[row] = corr;
                row_l[row] = row_l[row] * corr + sum;
                row_m[row] = mnew;
            }
        }
        __syncthreads();

        // ---- rescale O, then O += P * V ----
#pragma unroll
        for (int mt = 0; mt < 4; mt++) {
            float cr0 = row_c[mt * 16 + g];
            float cr1 = row_c[mt * 16 + 8 + g];
#pragma unroll
            for (int nf = 0; nf < 4; nf++) {
                o[mt][nf][0] *= cr0; o[mt][nf][1] *= cr0;
                o[mt][nf][2] *= cr1; o[mt][nf][3] *= cr1;
            }
        }
#pragma unroll
        for (int k0 = 0; k0 < BN; k0 += 8) {
            unsigned b0r[4], b1r[4];
#pragma unroll
            for (int nf = 0; nf < 4; nf++) {
                b0r[nf] = __float_as_uint(Vs[(k0 + t) * QPAD + dw + nf * 8 + g]);
                b1r[nf] = __float_as_uint(Vs[(k0 + t + 4) * QPAD + dw + nf * 8 + g]);
            }
#pragma unroll
            for (int mt = 0; mt < 4; mt++) {
                const float* prow = Ps + mt * 16 * PPAD + k0;
                unsigned a0 = __float_as_uint(prow[g * PPAD + t]);
                unsigned a1 = __float_as_uint(prow[(g + 8) * PPAD + t]);
                unsigned a2 = __float_as_uint(prow[g * PPAD + t + 4]);
                unsigned a3 = __float_as_uint(prow[(g + 8) * PPAD + t + 4]);
#pragma unroll
                for (int nf = 0; nf < 4; nf++)
                    mma_tf32(o[mt][nf], a0, a1, a2, a3, b0r[nf], b1r[nf]);
            }
        }
        __syncthreads();
    }

    // ---- epilogue: out[b][d][token] = O / l ----
#pragma unroll
    for (int mt = 0; mt < 4; mt++) {
        int r0 = mt * 16 + g, r1 = r0 + 8;
        float il0 = 1.f / row_l[r0];
        float il1 = 1.f / row_l[r1];
#pragma unroll
        for (int nf = 0; nf < 4; nf++) {
            int d = dw + nf * 8 + 2 * t;
            size_t base = ((size_t)batch * DDIM + d) * NTOK + m0g;
            out[base + r0]        = o[mt][nf][0] * il0;
            out[base + NTOK + r0] = o[mt][nf][1] * il0;
            out[base + r1]        = o[mt][nf][2] * il1;
            out[base + NTOK + r1] = o[mt][nf][3] * il1;
        }
    }
}

static const int ATTN_SMEM_BYTES = (3 * BM * QPAD + BM * PPAD + 3 * BM) * (int)sizeof(float);

extern "C" void kernel_launch(void* const* d_in, const int* in_sizes, int n_in,
                              void* d_out, int out_size) {
    const float* x  = (const float*)d_in[0];
    const float* Wq = (const float*)d_in[1];
    const float* Wk = (const float*)d_in[2];
    const float* Wv = (const float*)d_in[3];
    float* out = (float*)d_out;

    dim3 gp(NTOK / 128, 12, NBATCH);   // 12 = 3 matrices * 4 d-tiles
    qkv_proj_kernel<<<gp, 256>>>(x, Wq, Wk, Wv);

    cudaFuncSetAttribute(attn_kernel, cudaFuncAttributeMaxDynamicSharedMemorySize,
                         ATTN_SMEM_BYTES);
    dim3 ga(NTOK / BM, NBATCH);
    attn_kernel<<<ga, 256, ATTN_SMEM_BYTES>>>(out);
}

// round 2
// speedup vs baseline: 1.3896x; 1.3896x over previous
#include <cuda_runtime.h>

#define NBATCH 8
#define NTOK   4096
#define DDIM   256
#define BM     64
#define BN     32
#define NITER  (NTOK / BN)   // 128
#define KPAD   260   // Q/K rows: bank (4g+t) conflict-free
#define VPAD   264   // V rows:  bank (8t+g) conflict-free
#define PPAD   36    // P tile:  bank (4g+t) conflict-free

// Scratch for Q, K, V: (8, 4096, 256) fp32, token-major, PRE-ROUNDED to TF32.
// Q additionally pre-scaled by 1/sqrt(256) = 1/16.
__device__ float g_q[(size_t)NBATCH * NTOK * DDIM];
__device__ float g_k[(size_t)NBATCH * NTOK * DDIM];
__device__ float g_v[(size_t)NBATCH * NTOK * DDIM];

__device__ __forceinline__ unsigned f2tf32(float f) {
    unsigned u;
    asm("cvt.rna.tf32.f32 %0, %1;" : "=r"(u) : "f"(f));
    return u;
}
__device__ __forceinline__ float tf32f(float f) { return __uint_as_float(f2tf32(f)); }

__device__ __forceinline__ void mma_tf32(float* c, unsigned a0, unsigned a1, unsigned a2,
                                         unsigned a3, unsigned b0, unsigned b1) {
    asm volatile(
        "mma.sync.aligned.m16n8k8.row.col.f32.tf32.tf32.f32 "
        "{%0,%1,%2,%3},{%4,%5,%6,%7},{%8,%9},{%0,%1,%2,%3};\n"
        : "+f"(c[0]), "+f"(c[1]), "+f"(c[2]), "+f"(c[3])
        : "r"(a0), "r"(a1), "r"(a2), "r"(a3), "r"(b0), "r"(b1));
}

__device__ __forceinline__ void cp16(float* dst, const float* src) {
    unsigned d = (unsigned)__cvta_generic_to_shared(dst);
    asm volatile("cp.async.cg.shared.global [%0], [%1], 16;" :: "r"(d), "l"(src));
}
#define CP_COMMIT() asm volatile("cp.async.commit_group;")
#define CP_WAIT1()  asm volatile("cp.async.wait_group 1;")

// ============================================================================
// Kernel 1: QKV projection -> TF32-rounded scratch (Q pre-scaled by 1/16).
// ============================================================================
__global__ __launch_bounds__(256) void qkv_proj_kernel(
    const float* __restrict__ x, const float* __restrict__ Wq,
    const float* __restrict__ Wk, const float* __restrict__ Wv)
{
    __shared__ float Xs[32][132];
    __shared__ float Ws[64][36];

    const int batch = blockIdx.z;
    const int n0    = blockIdx.x * 128;
    const int mat   = blockIdx.y >> 2;
    const int d0    = (blockIdx.y & 3) * 64;
    const float* W  = (mat == 0) ? Wq : ((mat == 1) ? Wk : Wv);
    float* outg     = (mat == 0) ? g_q : ((mat == 1) ? g_k : g_v);
    const float osc = (mat == 0) ? 0.0625f : 1.0f;

    const int tid = threadIdx.x, warp = tid >> 5, lane = tid & 31;
    const int g = lane >> 2, t = lane & 3;
    const int m0 = warp * 16;

    float acc[8][4];
#pragma unroll
    for (int nf = 0; nf < 8; nf++)
#pragma unroll
        for (int i = 0; i < 4; i++) acc[nf][i] = 0.f;

    for (int kc = 0; kc < 256; kc += 32) {
#pragma unroll
        for (int i = tid; i < 1024; i += 256) {
            int r = i >> 5, cq = i & 31;
            float4 v = *(const float4*)(x + ((size_t)(batch * 256 + kc + r)) * 4096 + n0 + cq * 4);
            float* d = &Xs[r][cq * 4];
            d[0] = tf32f(v.x); d[1] = tf32f(v.y); d[2] = tf32f(v.z); d[3] = tf32f(v.w);
        }
#pragma unroll
        for (int i = tid; i < 512; i += 256) {
            int r = i >> 3, cq = i & 7;
            float4 v = *(const float4*)(W + (size_t)(d0 + r) * 256 + kc + cq * 4);
            float* d = &Ws[r][cq * 4];
            d[0] = tf32f(v.x); d[1] = tf32f(v.y); d[2] = tf32f(v.z); d[3] = tf32f(v.w);
        }
        __syncthreads();

#pragma unroll
        for (int k8 = 0; k8 < 32; k8 += 8) {
            unsigned a0 = __float_as_uint(Xs[k8 + t][m0 + g]);
            unsigned a1 = __float_as_uint(Xs[k8 + t][m0 + 8 + g]);
            unsigned a2 = __float_as_uint(Xs[k8 + t + 4][m0 + g]);
            unsigned a3 = __float_as_uint(Xs[k8 + t + 4][m0 + 8 + g]);
#pragma unroll
            for (int nf = 0; nf < 8; nf++) {
                unsigned b0 = __float_as_uint(Ws[nf * 8 + g][k8 + t]);
                unsigned b1 = __float_as_uint(Ws[nf * 8 + g][k8 + t + 4]);
                mma_tf32(acc[nf], a0, a1, a2, a3, b0, b1);
            }
        }
        __syncthreads();
    }

    float* ob = outg + ((size_t)batch * NTOK + n0 + m0) * DDIM + d0;
#pragma unroll
    for (int nf = 0; nf < 8; nf++) {
        int d = nf * 8 + 2 * t;
        *(float2*)(ob + (size_t)g * DDIM + d) =
            make_float2(tf32f(acc[nf][0] * osc), tf32f(acc[nf][1] * osc));
        *(float2*)(ob + (size_t)(g + 8) * DDIM + d) =
            make_float2(tf32f(acc[nf][2] * osc), tf32f(acc[nf][3] * osc));
    }
}

// ============================================================================
// Kernel 2: flash attention, BM=64 queries, BN=32 keys per iter, 128 iters.
// cp.async double-buffered K/V. 8 warps.
//   S phase:  warps 4(m) x 2(n), each 16x16 of the 64x32 S tile.
//   PV phase: each warp owns 32 d-columns, all 64 rows.
// ============================================================================
__global__ __launch_bounds__(256) void attn_kernel(float* __restrict__ out)
{
    extern __shared__ float smf[];
    float* Qs    = smf;                        // 64 * 260
    float* Ks    = Qs + BM * KPAD;             // 2 * 32 * 260
    float* Vs    = Ks + 2 * BN * KPAD;         // 2 * 32 * 264
    float* Ps    = Vs + 2 * BN * VPAD;         // 64 * 36
    float* row_m = Ps + BM * PPAD;             // 64
    float* row_l = row_m + BM;                 // 64
    float* row_c = row_l + BM;                 // 64

    const int batch = blockIdx.y;
    const int m0g   = blockIdx.x * BM;
    const int tid = threadIdx.x, warp = tid >> 5, lane = tid & 31;
    const int g = lane >> 2, t = lane & 3;
    const int wm = warp >> 1, wn = warp & 1;
    const int dw = warp * 32;

    const float* Qg = g_q + ((size_t)batch * NTOK + m0g) * DDIM;
    const float* Kg = g_k + (size_t)batch * NTOK * DDIM;
    const float* Vg = g_v + (size_t)batch * NTOK * DDIM;

    // Group 0: Q tile + KV tile 0
#pragma unroll
    for (int ii = 0; ii < 16; ii++) {
        int i = tid + ii * 256;            // 64 rows x 64 chunks
        int r = i >> 6, c = i & 63;
        cp16(Qs + r * KPAD + c * 4, Qg + (size_t)r * DDIM + c * 4);
    }
#pragma unroll
    for (int ii = 0; ii < 8; ii++) {
        int i = tid + ii * 256;            // 32 rows x 64 chunks
        int r = i >> 6, c = i & 63;
        cp16(Ks + r * KPAD + c * 4, Kg + (size_t)r * DDIM + c * 4);
        cp16(Vs + r * VPAD + c * 4, Vg + (size_t)r * DDIM + c * 4);
    }
    CP_COMMIT();
    // Group 1: KV tile 1
#pragma unroll
    for (int ii = 0; ii < 8; ii++) {
        int i = tid + ii * 256;
        int r = i >> 6, c = i & 63;
        cp16(Ks + BN * KPAD + r * KPAD + c * 4, Kg + (size_t)(BN + r) * DDIM + c * 4);
        cp16(Vs + BN * VPAD + r * VPAD + c * 4, Vg + (size_t)(BN + r) * DDIM + c * 4);
    }
    CP_COMMIT();

    if (tid < BM) { row_m[tid] = -1e30f; row_l[tid] = 0.f; }

    float o[4][4][4];
#pragma unroll
    for (int mt = 0; mt < 4; mt++)
#pragma unroll
        for (int nf = 0; nf < 4; nf++)
#pragma unroll
            for (int i = 0; i < 4; i++) o[mt][nf][i] = 0.f;

    for (int j = 0; j < NITER; j++) {
        CP_WAIT1();
        __syncthreads();
        const float* Kb = Ks + (j & 1) * BN * KPAD;
        const float* Vb = Vs + (j & 1) * BN * VPAD;

        // ---- S = Q K^T (pre-scaled) ----
        float s[2][4];
#pragma unroll
        for (int nf = 0; nf < 2; nf++)
#pragma unroll
            for (int i = 0; i < 4; i++) s[nf][i] = 0.f;

#pragma unroll
        for (int k0 = 0; k0 < DDIM; k0 += 8) {
            const float* qrow = Qs + wm * 16 * KPAD + k0;
            unsigned a0 = __float_as_uint(qrow[g * KPAD + t]);
            unsigned a1 = __float_as_uint(qrow[(g + 8) * KPAD + t]);
            unsigned a2 = __float_as_uint(qrow[g * KPAD + t + 4]);
            unsigned a3 = __float_as_uint(qrow[(g + 8) * KPAD + t + 4]);
#pragma unroll
            for (int nf = 0; nf < 2; nf++) {
                const float* krow = Kb + (wn * 16 + nf * 8) * KPAD + k0;
                unsigned b0 = __float_as_uint(krow[g * KPAD + t]);
                unsigned b1 = __float_as_uint(krow[g * KPAD + t + 4]);
                mma_tf32(s[nf], a0, a1, a2, a3, b0, b1);
            }
        }
#pragma unroll
        for (int nf = 0; nf < 2; nf++) {
            int col = wn * 16 + nf * 8 + 2 * t;
            int r = wm * 16 + g;
            Ps[r * PPAD + col]           = s[nf][0];
            Ps[r * PPAD + col + 1]       = s[nf][1];
            Ps[(r + 8) * PPAD + col]     = s[nf][2];
            Ps[(r + 8) * PPAD + col + 1] = s[nf][3];
        }
        __syncthreads();

        // ---- online softmax: warp w rows w*8..w*8+7; 4 lanes/row, 8 cols each ----
        {
            int row = warp * 8 + g;
            float* pr = Ps + row * PPAD + t * 8;
            float4 v0 = *(float4*)pr;
            float4 v1 = *(float4*)(pr + 4);
            float mx = fmaxf(fmaxf(fmaxf(v0.x, v0.y), fmaxf(v0.z, v0.w)),
                             fmaxf(fmaxf(v1.x, v1.y), fmaxf(v1.z, v1.w)));
            mx = fmaxf(mx, __shfl_xor_sync(0xffffffffu, mx, 1));
            mx = fmaxf(mx, __shfl_xor_sync(0xffffffffu, mx, 2));
            float mold = row_m[row];
            float mnew = fmaxf(mold, mx);
            float e0 = __expf(v0.x - mnew), e1 = __expf(v0.y - mnew);
            float e2 = __expf(v0.z - mnew), e3 = __expf(v0.w - mnew);
            float e4 = __expf(v1.x - mnew), e5 = __expf(v1.y - mnew);
            float e6 = __expf(v1.z - mnew), e7 = __expf(v1.w - mnew);
            float sum = (e0 + e1) + (e2 + e3) + ((e4 + e5) + (e6 + e7));
            v0.x = tf32f(e0); v0.y = tf32f(e1); v0.z = tf32f(e2); v0.w = tf32f(e3);
            v1.x = tf32f(e4); v1.y = tf32f(e5); v1.z = tf32f(e6); v1.w = tf32f(e7);
            *(float4*)pr = v0;
            *(float4*)(pr + 4) = v1;
            sum += __shfl_xor_sync(0xffffffffu, sum, 1);
            sum += __shfl_xor_sync(0xffffffffu, sum, 2);
            if (t == 0) {
                float corr = __expf(mold - mnew);
                row_c[row] = corr;
                row_l[row] = row_l[row] * corr + sum;
                row_m[row] = mnew;
            }
        }
        __syncthreads();

        // ---- rescale O, then O += P * V ----
#pragma unroll
        for (int mt = 0; mt < 4; mt++) {
            float cr0 = row_c[mt * 16 + g];
            float cr1 = row_c[mt * 16 + 8 + g];
#pragma unroll
            for (int nf = 0; nf < 4; nf++) {
                o[mt][nf][0] *= cr0; o[mt][nf][1] *= cr0;
                o[mt][nf][2] *= cr1; o[mt][nf][3] *= cr1;
            }
        }
#pragma unroll
        for (int k0 = 0; k0 < BN; k0 += 8) {
            unsigned b0r[4], b1r[4];
#pragma unroll
            for (int nf = 0; nf < 4; nf++) {
                b0r[nf] = __float_as_uint(Vb[(k0 + t) * VPAD + dw + nf * 8 + g]);
                b1r[nf] = __float_as_uint(Vb[(k0 + t + 4) * VPAD + dw + nf * 8 + g]);
            }
#pragma unroll
            for (int mt = 0; mt < 4; mt++) {
                const float* prow = Ps + mt * 16 * PPAD + k0;
                unsigned a0 = __float_as_uint(prow[g * PPAD + t]);
                unsigned a1 = __float_as_uint(prow[(g + 8) * PPAD + t]);
                unsigned a2 = __float_as_uint(prow[g * PPAD + t + 4]);
                unsigned a3 = __float_as_uint(prow[(g + 8) * PPAD + t + 4]);
#pragma unroll
                for (int nf = 0; nf < 4; nf++)
                    mma_tf32(o[mt][nf], a0, a1, a2, a3, b0r[nf], b1r[nf]);
            }
        }
        __syncthreads();

        // ---- prefetch KV tile j+2 into the buffer just freed ----
        if (j + 2 < NITER) {
            float* Kd = Ks + (j & 1) * BN * KPAD;
            float* Vd = Vs + (j & 1) * BN * VPAD;
            const float* Kgs = Kg + (size_t)(j + 2) * BN * DDIM;
            const float* Vgs = Vg + (size_t)(j + 2) * BN * DDIM;
#pragma unroll
            for (int ii = 0; ii < 8; ii++) {
                int i = tid + ii * 256;
                int r = i >> 6, c = i & 63;
                cp16(Kd + r * KPAD + c * 4, Kgs + (size_t)r * DDIM + c * 4);
                cp16(Vd + r * VPAD + c * 4, Vgs + (size_t)r * DDIM + c * 4);
            }
        }
        CP_COMMIT();
    }

    // ---- epilogue: out[b][d][token] = O / l ----
#pragma unroll
    for (int mt = 0; mt < 4; mt++) {
        int r0 = mt * 16 + g, r1 = r0 + 8;
        float il0 = 1.f / row_l[r0];
        float il1 = 1.f / row_l[r1];
#pragma unroll
        for (int nf = 0; nf < 4; nf++) {
            int d = dw + nf * 8 + 2 * t;
            size_t base = ((size_t)batch * DDIM + d) * NTOK + m0g;
            out[base + r0]        = o[mt][nf][0] * il0;
            out[base + NTOK + r0] = o[mt][nf][1] * il0;
            out[base + r1]        = o[mt][nf][2] * il1;
            out[base + NTOK + r1] = o[mt][nf][3] * il1;
        }
    }
}

static const int ATTN_SMEM_BYTES =
    (BM * KPAD + 2 * BN * KPAD + 2 * BN * VPAD + BM * PPAD + 3 * BM) * (int)sizeof(float);

extern "C" void kernel_launch(void* const* d_in, const int* in_sizes, int n_in,
                              void* d_out, int out_size) {
    const float* x  = (const float*)d_in[0];
    const float* Wq = (const float*)d_in[1];
    const float* Wk = (const float*)d_in[2];
    const float* Wv = (const float*)d_in[3];
    float* out = (float*)d_out;

    dim3 gp(NTOK / 128, 12, NBATCH);
    qkv_proj_kernel<<<gp, 256>>>(x, Wq, Wk, Wv);

    cudaFuncSetAttribute(attn_kernel, cudaFuncAttributeMaxDynamicSharedMemorySize,
                         ATTN_SMEM_BYTES);
    dim3 ga(NTOK / BM, NBATCH);
    attn_kernel<<<ga, 256, ATTN_SMEM_BYTES>>>(out);
}

// round 4
// speedup vs baseline: 1.6650x; 1.1982x over previous
#include <cuda_runtime.h>
#include <cstdint>

#define NBATCH 8
#define NTOK   4096
#define DDIM   256
#define BM     64
#define BN     32
#define NITER  (NTOK / BN)   // 128
#define KPAD   260   // Q/K rows: bank (4g+t) conflict-free
#define VPAD   264   // V rows:  bank (8t+g) conflict-free
#define PPAD   36    // P tile:  bank (4g+t) conflict-free

// Scratch: Q,K,V token-major [b][tok][d], TF32-rounded; Q pre-scaled by 1/16.
__device__ float g_q[(size_t)NBATCH * NTOK * DDIM];
__device__ float g_k[(size_t)NBATCH * NTOK * DDIM];
__device__ float g_v[(size_t)NBATCH * NTOK * DDIM];

__device__ __forceinline__ unsigned f2tf32(float f) {
    unsigned u; asm("cvt.rna.tf32.f32 %0, %1;" : "=r"(u) : "f"(f)); return u;
}
__device__ __forceinline__ float tf32f(float f) { return __uint_as_float(f2tf32(f)); }

__device__ __forceinline__ void mma_tf32(float* c, unsigned a0, unsigned a1, unsigned a2,
                                         unsigned a3, unsigned b0, unsigned b1) {
    asm volatile(
        "mma.sync.aligned.m16n8k8.row.col.f32.tf32.tf32.f32 "
        "{%0,%1,%2,%3},{%4,%5,%6,%7},{%8,%9},{%0,%1,%2,%3};\n"
        : "+f"(c[0]), "+f"(c[1]), "+f"(c[2]), "+f"(c[3])
        : "r"(a0), "r"(a1), "r"(a2), "r"(a3), "r"(b0), "r"(b1));
}

__device__ __forceinline__ void cp16(float* dst, const float* src) {
    unsigned d = (unsigned)__cvta_generic_to_shared(dst);
    asm volatile("cp.async.cg.shared.global [%0], [%1], 16;" :: "r"(d), "l"(src));
}
#define CP_COMMIT() asm volatile("cp.async.commit_group;" ::: "memory")
#define CP_WAIT1()  asm volatile("cp.async.wait_group 1;" ::: "memory")
#define BAR(id)     asm volatile("bar.sync %0, 256;" :: "r"(id) : "memory")

// ============================================================================
// Kernel 1: QKV projection (unchanged from R2). Q pre-scaled 1/16.
// ============================================================================
__global__ __launch_bounds__(256) void qkv_proj_kernel(
    const float* __restrict__ x, const float* __restrict__ Wq,
    const float* __restrict__ Wk, const float* __restrict__ Wv)
{
    __shared__ float Xs[32][132];
    __shared__ float Ws[64][36];

    const int batch = blockIdx.z;
    const int n0    = blockIdx.x * 128;
    const int mat   = blockIdx.y >> 2;
    const int d0    = (blockIdx.y & 3) * 64;
    const float* W  = (mat == 0) ? Wq : ((mat == 1) ? Wk : Wv);
    float* outg     = (mat == 0) ? g_q : ((mat == 1) ? g_k : g_v);
    const float osc = (mat == 0) ? 0.0625f : 1.0f;

    const int tid = threadIdx.x, warp = tid >> 5, lane = tid & 31;
    const int g = lane >> 2, t = lane & 3;
    const int m0 = warp * 16;

    float acc[8][4];
#pragma unroll
    for (int nf = 0; nf < 8; nf++)
#pragma unroll
        for (int i = 0; i < 4; i++) acc[nf][i] = 0.f;

    for (int kc = 0; kc < 256; kc += 32) {
#pragma unroll
        for (int i = tid; i < 1024; i += 256) {
            int r = i >> 5, cq = i & 31;
            float4 v = *(const float4*)(x + ((size_t)(batch * 256 + kc + r)) * 4096 + n0 + cq * 4);
            float* d = &Xs[r][cq * 4];
            d[0] = tf32f(v.x); d[1] = tf32f(v.y); d[2] = tf32f(v.z); d[3] = tf32f(v.w);
        }
#pragma unroll
        for (int i = tid; i < 512; i += 256) {
            int r = i >> 3, cq = i & 7;
            float4 v = *(const float4*)(W + (size_t)(d0 + r) * 256 + kc + cq * 4);
            float* d = &Ws[r][cq * 4];
            d[0] = tf32f(v.x); d[1] = tf32f(v.y); d[2] = tf32f(v.z); d[3] = tf32f(v.w);
        }
        __syncthreads();

#pragma unroll
        for (int k8 = 0; k8 < 32; k8 += 8) {
            unsigned a0 = __float_as_uint(Xs[k8 + t][m0 + g]);
            unsigned a1 = __float_as_uint(Xs[k8 + t][m0 + 8 + g]);
            unsigned a2 = __float_as_uint(Xs[k8 + t + 4][m0 + g]);
            unsigned a3 = __float_as_uint(Xs[k8 + t + 4][m0 + 8 + g]);
#pragma unroll
            for (int nf = 0; nf < 8; nf++) {
                unsigned b0 = __float_as_uint(Ws[nf * 8 + g][k8 + t]);
                unsigned b1 = __float_as_uint(Ws[nf * 8 + g][k8 + t + 4]);
                mma_tf32(acc[nf], a0, a1, a2, a3, b0, b1);
            }
        }
        __syncthreads();
    }

    float* ob = outg + ((size_t)batch * NTOK + n0 + m0) * DDIM + d0;
#pragma unroll
    for (int nf = 0; nf < 8; nf++) {
        int d = nf * 8 + 2 * t;
        *(float2*)(ob + (size_t)g * DDIM + d) =
            make_float2(tf32f(acc[nf][0] * osc), tf32f(acc[nf][1] * osc));
        *(float2*)(ob + (size_t)(g + 8) * DDIM + d) =
            make_float2(tf32f(acc[nf][2] * osc), tf32f(acc[nf][3] * osc));
    }
}

// ============================================================================
// Kernel 2: warp-specialized flash attention (no-max softmax), 512 threads.
//   warps 0-7  (S-half):  S_j = Q K_j^T -> exp -> P_j (double buffered)
//   warps 8-15 (PV-half): O += P_{j-1} V_{j-1}
// One __syncthreads per iteration hands P across; each half runs its own
// cp.async stream (S: K, PV: V) with intra-half named barriers for WAR.
// ============================================================================
__global__ __launch_bounds__(512) void attn_kernel(float* __restrict__ out)
{
    extern __shared__ float smf[];
    float* Qs     = smf;                         // 64 * 260
    float* Ks     = Qs + BM * KPAD;              // 2 * 32 * 260
    float* Vs     = Ks + 2 * BN * KPAD;          // 2 * 32 * 264
    float* Ps     = Vs + 2 * BN * VPAD;          // 2 * 64 * 36
    float* row_l2 = Ps + 2 * BM * PPAD;          // 2 * 64

    const int batch = blockIdx.y;
    const int m0g   = blockIdx.x * BM;
    const int tid = threadIdx.x, warp = tid >> 5, lane = tid & 31;
    const int g = lane >> 2, t = lane & 3;
    const int lt = tid & 255;                    // local tid within half

    const float* Qg = g_q + ((size_t)batch * NTOK + m0g) * DDIM;
    const float* Kg = g_k + (size_t)batch * NTOK * DDIM;
    const float* Vg = g_v + (size_t)batch * NTOK * DDIM;

    // ---- initial loads ----
    if (tid < 256) {
        // Q tile + K0 (group 0), K1 (group 1)
#pragma unroll
        for (int ii = 0; ii < 16; ii++) {
            int i = lt + ii * 256;
            int r = i >> 6, c = i & 63;
            cp16(Qs + r * KPAD + c * 4, Qg + (size_t)r * DDIM + c * 4);
        }
#pragma unroll
        for (int ii = 0; ii < 8; ii++) {
            int i = lt + ii * 256;
            int r = i >> 6, c = i & 63;
            cp16(Ks + r * KPAD + c * 4, Kg + (size_t)r * DDIM + c * 4);
        }
        CP_COMMIT();
#pragma unroll
        for (int ii = 0; ii < 8; ii++) {
            int i = lt + ii * 256;
            int r = i >> 6, c = i & 63;
            cp16(Ks + BN * KPAD + r * KPAD + c * 4, Kg + (size_t)(BN + r) * DDIM + c * 4);
        }
        CP_COMMIT();
    } else {
        // V0 (group 0), V1 (group 1)
#pragma unroll
        for (int ii = 0; ii < 8; ii++) {
            int i = lt + ii * 256;
            int r = i >> 6, c = i & 63;
            cp16(Vs + r * VPAD + c * 4, Vg + (size_t)r * DDIM + c * 4);
        }
        CP_COMMIT();
#pragma unroll
        for (int ii = 0; ii < 8; ii++) {
            int i = lt + ii * 256;
            int r = i >> 6, c = i & 63;
            cp16(Vs + BN * VPAD + r * VPAD + c * 4, Vg + (size_t)(BN + r) * DDIM + c * 4);
        }
        CP_COMMIT();
    }

    // S-half state
    const int wm = warp >> 1, wn = warp & 1;     // valid for warps 0-7
    float sum0 = 0.f, sum1 = 0.f;
    // PV-half state
    const int dw = (warp - 8) * 32;              // valid for warps 8-15
    float o[4][4][4];
#pragma unroll
    for (int mt = 0; mt < 4; mt++)
#pragma unroll
        for (int nf = 0; nf < 4; nf++)
#pragma unroll
            for (int i = 0; i < 4; i++) o[mt][nf][i] = 0.f;

    for (int j = 0; j <= NITER; j++) {
        __syncthreads();
        if (tid < 256) {
            if (j < NITER) {
                CP_WAIT1();                      // K_j arrived (Q too on j=0)
                BAR(1);                          // visibility across S-half

                const float* Kb = Ks + (j & 1) * BN * KPAD;
                float s[2][4];
#pragma unroll
                for (int nf = 0; nf < 2; nf++)
#pragma unroll
                    for (int i = 0; i < 4; i++) s[nf][i] = 0.f;

#pragma unroll
                for (int k0 = 0; k0 < DDIM; k0 += 8) {
                    const float* qrow = Qs + wm * 16 * KPAD + k0;
                    unsigned a0 = __float_as_uint(qrow[g * KPAD + t]);
                    unsigned a1 = __float_as_uint(qrow[(g + 8) * KPAD + t]);
                    unsigned a2 = __float_as_uint(qrow[g * KPAD + t + 4]);
                    unsigned a3 = __float_as_uint(qrow[(g + 8) * KPAD + t + 4]);
#pragma unroll
                    for (int nf = 0; nf < 2; nf++) {
                        const float* krow = Kb + (wn * 16 + nf * 8) * KPAD + k0;
                        unsigned b0 = __float_as_uint(krow[g * KPAD + t]);
                        unsigned b1 = __float_as_uint(krow[g * KPAD + t + 4]);
                        mma_tf32(s[nf], a0, a1, a2, a3, b0, b1);
                    }
                }

                // exp (no max), accumulate row sums, store P_j
                float* Pb = Ps + (j & 1) * BM * PPAD;
#pragma unroll
                for (int nf = 0; nf < 2; nf++) {
                    float p0 = __expf(s[nf][0]), p1 = __expf(s[nf][1]);
                    float p2 = __expf(s[nf][2]), p3 = __expf(s[nf][3]);
                    sum0 += p0 + p1;
                    sum1 += p2 + p3;
                    int r = wm * 16 + g, col = wn * 16 + nf * 8 + 2 * t;
                    *(float2*)(Pb + r * PPAD + col) =
                        make_float2(tf32f(p0), tf32f(p1));
                    *(float2*)(Pb + (r + 8) * PPAD + col) =
                        make_float2(tf32f(p2), tf32f(p3));
                }

                BAR(1);                          // all S-warps done with K_j
                if (j + 2 < NITER) {
                    float* Kd = Ks + (j & 1) * BN * KPAD;
                    const float* Kgs = Kg + (size_t)(j + 2) * BN * DDIM;
#pragma unroll
                    for (int ii = 0; ii < 8; ii++) {
                        int i = lt + ii * 256;
                        int r = i >> 6, c = i & 63;
                        cp16(Kd + r * KPAD + c * 4, Kgs + (size_t)r * DDIM + c * 4);
                    }
                }
                CP_COMMIT();
            }
        } else {
            if (j >= 1) {
                CP_WAIT1();                      // V_{j-1} arrived
                BAR(2);

                const float* Vb = Vs + ((j - 1) & 1) * BN * VPAD;
                const float* Pb = Ps + ((j - 1) & 1) * BM * PPAD;
#pragma unroll
                for (int k0 = 0; k0 < BN; k0 += 8) {
                    unsigned b0r[4], b1r[4];
#pragma unroll
                    for (int nf = 0; nf < 4; nf++) {
                        b0r[nf] = __float_as_uint(Vb[(k0 + t) * VPAD + dw + nf * 8 + g]);
                        b1r[nf] = __float_as_uint(Vb[(k0 + t + 4) * VPAD + dw + nf * 8 + g]);
                    }
#pragma unroll
                    for (int mt = 0; mt < 4; mt++) {
                        const float* prow = Pb + mt * 16 * PPAD + k0;
                        unsigned a0 = __float_as_uint(prow[g * PPAD + t]);
                        unsigned a1 = __float_as_uint(prow[(g + 8) * PPAD + t]);
                        unsigned a2 = __float_as_uint(prow[g * PPAD + t + 4]);
                        unsigned a3 = __float_as_uint(prow[(g + 8) * PPAD + t + 4]);
#pragma unroll
                        for (int nf = 0; nf < 4; nf++)
                            mma_tf32(o[mt][nf], a0, a1, a2, a3, b0r[nf], b1r[nf]);
                    }
                }

                BAR(2);                          // all PV-warps done with V_{j-1}
                if (j + 1 < NITER) {
                    float* Vd = Vs + ((j + 1) & 1) * BN * VPAD;
                    const float* Vgs = Vg + (size_t)(j + 1) * BN * DDIM;
#pragma unroll
                    for (int ii = 0; ii < 8; ii++) {
                        int i = lt + ii * 256;
                        int r = i >> 6, c = i & 63;
                        cp16(Vd + r * VPAD + c * 4, Vgs + (size_t)r * DDIM + c * 4);
                    }
                }
                CP_COMMIT();
            }
        }
    }

    // ---- row-sum reduction (S-half) ----
    if (tid < 256) {
        sum0 += __shfl_xor_sync(0xffffffffu, sum0, 1);
        sum0 += __shfl_xor_sync(0xffffffffu, sum0, 2);
        sum1 += __shfl_xor_sync(0xffffffffu, sum1, 1);
        sum1 += __shfl_xor_sync(0xffffffffu, sum1, 2);
        if (t == 0) {
            row_l2[wn * 64 + wm * 16 + g]     = sum0;
            row_l2[wn * 64 + wm * 16 + 8 + g] = sum1;
        }
    }
    __syncthreads();

    // ---- epilogue: out[b][d][token] = O / l  (PV-half) ----
    if (tid >= 256) {
#pragma unroll
        for (int mt = 0; mt < 4; mt++) {
            int r0 = mt * 16 + g, r1 = r0 + 8;
            float il0 = 1.f / (row_l2[r0] + row_l2[64 + r0]);
            float il1 = 1.f / (row_l2[r1] + row_l2[64 + r1]);
#pragma unroll
            for (int nf = 0; nf < 4; nf++) {
                int d = dw + nf * 8 + 2 * t;
                size_t base = ((size_t)batch * DDIM + d) * NTOK + m0g;
                out[base + r0]        = o[mt][nf][0] * il0;
                out[base + NTOK + r0] = o[mt][nf][1] * il0;
                out[base + r1]        = o[mt][nf][2] * il1;
                out[base + NTOK + r1] = o[mt][nf][3] * il1;
            }
        }
    }
}

static const int ATTN_SMEM_BYTES =
    (BM * KPAD + 2 * BN * KPAD + 2 * BN * VPAD + 2 * BM * PPAD + 2 * BM) * (int)sizeof(float);

extern "C" void kernel_launch(void* const* d_in, const int* in_sizes, int n_in,
                              void* d_out, int out_size) {
    const float* x  = (const float*)d_in[0];
    const float* Wq = (const float*)d_in[1];
    const float* Wk = (const float*)d_in[2];
    const float* Wv = (const float*)d_in[3];
    float* out = (float*)d_out;

    dim3 gp(NTOK / 128, 12, NBATCH);
    qkv_proj_kernel<<<gp, 256>>>(x, Wq, Wk, Wv);

    cudaFuncSetAttribute(attn_kernel, cudaFuncAttributeMaxDynamicSharedMemorySize,
                         ATTN_SMEM_BYTES);
    dim3 ga(NTOK / BM, NBATCH);
    attn_kernel<<<ga, 512, ATTN_SMEM_BYTES>>>(out);
}

// round 6
// speedup vs baseline: 2.9466x; 1.7698x over previous
#include <cuda_runtime.h>
#include <cuda_fp16.h>
#include <cstdint>

#define NBATCH 8
#define NTOK   4096
#define DDIM   256
#define BM     64
#define BN     32
#define NITER  (NTOK / BN)   // 128
#define KP     264   // Q/K row pitch in halfs:  (KP/2)%8==4 -> conflict-free b32 frags
#define VP     40    // V/P row pitch in halfs:  (VP/2)%8==4 -> conflict-free

// fp16 scratch: Q,K token-major [b][tok][d]; V transposed [b][d][tok].
// Q pre-scaled by 1/sqrt(256)=1/16.
__device__ __half g_qh [(size_t)NBATCH * NTOK * DDIM];
__device__ __half g_kh [(size_t)NBATCH * NTOK * DDIM];
__device__ __half g_vTh[(size_t)NBATCH * DDIM * NTOK];

// ---------- helpers ----------
__device__ __forceinline__ unsigned f2tf32(float f) {
    unsigned u; asm("cvt.rna.tf32.f32 %0, %1;" : "=r"(u) : "f"(f)); return u;
}
__device__ __forceinline__ float tf32f(float f) { return __uint_as_float(f2tf32(f)); }

__device__ __forceinline__ unsigned ldsu(const __half* p) {
    return *(const unsigned*)p;
}

// fp16 mma m16n8k16, fp32 accumulate.
// A(16x16 row): a0=(g,2t,2t+1) a1=(g+8,2t..) a2=(g,8+2t..) a3=(g+8,8+2t..)
// B(16x8 col):  b0=(k=2t,2t+1, n=g) b1=(k=8+2t.., n=g)
// C: c0=(g,2t) c1=(g,2t+1) c2=(g+8,2t) c3=(g+8,2t+1)
__device__ __forceinline__ void mma_f16(float* c, unsigned a0, unsigned a1, unsigned a2,
                                        unsigned a3, unsigned b0, unsigned b1) {
    asm volatile(
        "mma.sync.aligned.m16n8k16.row.col.f32.f16.f16.f32 "
        "{%0,%1,%2,%3},{%4,%5,%6,%7},{%8,%9},{%0,%1,%2,%3};\n"
        : "+f"(c[0]), "+f"(c[1]), "+f"(c[2]), "+f"(c[3])
        : "r"(a0), "r"(a1), "r"(a2), "r"(a3), "r"(b0), "r"(b1));
}

// tf32 mma (projection kernel)
__device__ __forceinline__ void mma_tf32(float* c, unsigned a0, unsigned a1, unsigned a2,
                                         unsigned a3, unsigned b0, unsigned b1) {
    asm volatile(
        "mma.sync.aligned.m16n8k8.row.col.f32.tf32.tf32.f32 "
        "{%0,%1,%2,%3},{%4,%5,%6,%7},{%8,%9},{%0,%1,%2,%3};\n"
        : "+f"(c[0]), "+f"(c[1]), "+f"(c[2]), "+f"(c[3])
        : "r"(a0), "r"(a1), "r"(a2), "r"(a3), "r"(b0), "r"(b1));
}

__device__ __forceinline__ void cp16(void* dst, const void* src) {
    unsigned d = (unsigned)__cvta_generic_to_shared(dst);
    asm volatile("cp.async.cg.shared.global [%0], [%1], 16;" :: "r"(d), "l"(src));
}
#define CP_COMMIT() asm volatile("cp.async.commit_group;" ::: "memory")
#define CP_WAIT1()  asm volatile("cp.async.wait_group 1;" ::: "memory")
#define BAR(id)     asm volatile("bar.sync %0, 256;" :: "r"(id) : "memory")

// ============================================================================
// Kernel 1: QKV projection (tf32 mma), outputs fp16. Q scaled 1/16, V -> vT.
// ============================================================================
__global__ __launch_bounds__(256) void qkv_proj_kernel(
    const float* __restrict__ x, const float* __restrict__ Wq,
    const float* __restrict__ Wk, const float* __restrict__ Wv)
{
    __shared__ float Xs[32][132];
    __shared__ float Ws[64][36];

    const int batch = blockIdx.z;
    const int n0    = blockIdx.x * 128;
    const int mat   = blockIdx.y >> 2;
    const int d0    = (blockIdx.y & 3) * 64;
    const float* W  = (mat == 0) ? Wq : ((mat == 1) ? Wk : Wv);
    const float osc = (mat == 0) ? 0.0625f : 1.0f;

    const int tid = threadIdx.x, warp = tid >> 5, lane = tid & 31;
    const int g = lane >> 2, t = lane & 3;
    const int m0 = warp * 16;

    float acc[8][4];
#pragma unroll
    for (int nf = 0; nf < 8; nf++)
#pragma unroll
        for (int i = 0; i < 4; i++) acc[nf][i] = 0.f;

    for (int kc = 0; kc < 256; kc += 32) {
#pragma unroll
        for (int i = tid; i < 1024; i += 256) {
            int r = i >> 5, cq = i & 31;
            float4 v = *(const float4*)(x + ((size_t)(batch * 256 + kc + r)) * 4096 + n0 + cq * 4);
            float* d = &Xs[r][cq * 4];
            d[0] = tf32f(v.x); d[1] = tf32f(v.y); d[2] = tf32f(v.z); d[3] = tf32f(v.w);
        }
#pragma unroll
        for (int i = tid; i < 512; i += 256) {
            int r = i >> 3, cq = i & 7;
            float4 v = *(const float4*)(W + (size_t)(d0 + r) * 256 + kc + cq * 4);
            float* d = &Ws[r][cq * 4];
            d[0] = tf32f(v.x); d[1] = tf32f(v.y); d[2] = tf32f(v.z); d[3] = tf32f(v.w);
        }
        __syncthreads();

#pragma unroll
        for (int k8 = 0; k8 < 32; k8 += 8) {
            unsigned a0 = __float_as_uint(Xs[k8 + t][m0 + g]);
            unsigned a1 = __float_as_uint(Xs[k8 + t][m0 + 8 + g]);
            unsigned a2 = __float_as_uint(Xs[k8 + t + 4][m0 + g]);
            unsigned a3 = __float_as_uint(Xs[k8 + t + 4][m0 + 8 + g]);
#pragma unroll
            for (int nf = 0; nf < 8; nf++) {
                unsigned b0 = __float_as_uint(Ws[nf * 8 + g][k8 + t]);
                unsigned b1 = __float_as_uint(Ws[nf * 8 + g][k8 + t + 4]);
                mma_tf32(acc[nf], a0, a1, a2, a3, b0, b1);
            }
        }
        __syncthreads();
    }

    if (mat != 2) {
        __half* outg = (mat == 0) ? g_qh : g_kh;
        __half* ob = outg + ((size_t)batch * NTOK + n0 + m0) * DDIM + d0;
#pragma unroll
        for (int nf = 0; nf < 8; nf++) {
            int d = nf * 8 + 2 * t;
            *(__half2*)(ob + (size_t)g * DDIM + d) =
                __floats2half2_rn(acc[nf][0] * osc, acc[nf][1] * osc);
            *(__half2*)(ob + (size_t)(g + 8) * DDIM + d) =
                __floats2half2_rn(acc[nf][2] * osc, acc[nf][3] * osc);
        }
    } else {
        __half* vb = g_vTh + (size_t)batch * DDIM * NTOK;
        int tok0 = n0 + m0;
#pragma unroll
        for (int nf = 0; nf < 8; nf++) {
            int d = d0 + nf * 8 + 2 * t;
            vb[(size_t)d * NTOK + tok0 + g]           = __float2half_rn(acc[nf][0]);
            vb[(size_t)(d + 1) * NTOK + tok0 + g]     = __float2half_rn(acc[nf][1]);
            vb[(size_t)d * NTOK + tok0 + 8 + g]       = __float2half_rn(acc[nf][2]);
            vb[(size_t)(d + 1) * NTOK + tok0 + 8 + g] = __float2half_rn(acc[nf][3]);
        }
    }
}

// ============================================================================
// Kernel 2: fp16 warp-specialized flash attention (no-max softmax), 512 thr.
//   warps 0-7  (S-half):  Q in registers; S_j = Q K_j^T -> exp -> P_j
//   warps 8-15 (PV-half): O += P_{j-1} V_{j-1}
// fr[64] is UNION storage: S-half = Q fragments, PV-half = O accumulators.
// ============================================================================
// smem half-offsets
#define SH_Q   0
#define SH_K   16896                   // 64*264
#define SH_V   (SH_K + 2 * 32 * KP)    // + 16896
#define SH_P   (SH_V + 2 * 256 * VP)   // + 20480
#define SH_END (SH_P + 2 * 64 * VP)    // + 5120 = 59392 halfs
#define ATTN_SMEM_BYTES (SH_END * 2 + 128 * 4)

__global__ __launch_bounds__(512) void attn_kernel(float* __restrict__ out)
{
    extern __shared__ __align__(16) __half smh[];
    __half* Qs = smh + SH_Q;
    __half* Ks = smh + SH_K;
    __half* Vs = smh + SH_V;
    __half* Ps = smh + SH_P;
    float* row_l2 = (float*)(smh + SH_END);     // 2 * 64 floats

    const int batch = blockIdx.y;
    const int m0g   = blockIdx.x * BM;
    const int tid = threadIdx.x, warp = tid >> 5, lane = tid & 31;
    const int g = lane >> 2, t = lane & 3;
    const int lt = tid & 255;

    const __half* Qg  = g_qh  + ((size_t)batch * NTOK + m0g) * DDIM;
    const __half* Kg  = g_kh  + (size_t)batch * NTOK * DDIM;
    const __half* VgT = g_vTh + (size_t)batch * DDIM * NTOK;

    // ---- initial cp.async ----
    if (tid < 256) {
        // group 0: Q (64 rows x 32 chunks) + K0 (32 x 32)
#pragma unroll
        for (int ii = 0; ii < 8; ii++) {
            int i = lt + ii * 256, r = i >> 5, c = i & 31;
            cp16(Qs + r * KP + c * 8, Qg + (size_t)r * DDIM + c * 8);
        }
#pragma unroll
        for (int ii = 0; ii < 4; ii++) {
            int i = lt + ii * 256, r = i >> 5, c = i & 31;
            cp16(Ks + r * KP + c * 8, Kg + (size_t)r * DDIM + c * 8);
        }
        CP_COMMIT();
        // group 1: K1
#pragma unroll
        for (int ii = 0; ii < 4; ii++) {
            int i = lt + ii * 256, r = i >> 5, c = i & 31;
            cp16(Ks + BN * KP + r * KP + c * 8, Kg + (size_t)(BN + r) * DDIM + c * 8);
        }
        CP_COMMIT();
    } else {
        // group 0: V0 (256 d-rows x 4 chunks of 16B), group 1: V1
#pragma unroll
        for (int ii = 0; ii < 4; ii++) {
            int i = lt + ii * 256, r = i >> 2, c = i & 3;
            cp16(Vs + r * VP + c * 8, VgT + (size_t)r * NTOK + c * 8);
        }
        CP_COMMIT();
#pragma unroll
        for (int ii = 0; ii < 4; ii++) {
            int i = lt + ii * 256, r = i >> 2, c = i & 3;
            cp16(Vs + 256 * VP + r * VP + c * 8, VgT + (size_t)r * NTOK + BN + c * 8);
        }
        CP_COMMIT();
    }

    const int wm = warp >> 1, wn = warp & 1;     // S-half roles
    const int dw = (warp - 8) * 32;              // PV-half d slice
    float sum0 = 0.f, sum1 = 0.f;

    // Union register file: S-half = Q fragments (bits), PV-half = O accum.
    float fr[64];
#pragma unroll
    for (int i = 0; i < 64; i++) fr[i] = 0.f;

    for (int j = 0; j <= NITER; j++) {
        __syncthreads();
        if (tid < 256) {
            if (j < NITER) {
                CP_WAIT1();                      // K_j (and Q on j=0) arrived
                BAR(1);

                if (j == 0) {
                    // load Q fragments once: 16 k-steps x 4 regs
                    const __half* q0 = Qs + (wm * 16 + g) * KP + 2 * t;
                    const __half* q1 = q0 + 8 * KP;
#pragma unroll
                    for (int s = 0; s < 16; s++) {
                        fr[s * 4 + 0] = __uint_as_float(ldsu(q0 + s * 16));
                        fr[s * 4 + 1] = __uint_as_float(ldsu(q1 + s * 16));
                        fr[s * 4 + 2] = __uint_as_float(ldsu(q0 + s * 16 + 8));
                        fr[s * 4 + 3] = __uint_as_float(ldsu(q1 + s * 16 + 8));
                    }
                }

                const __half* Kb = Ks + (j & 1) * BN * KP;
                float s2[2][4];
#pragma unroll
                for (int nf = 0; nf < 2; nf++)
#pragma unroll
                    for (int i = 0; i < 4; i++) s2[nf][i] = 0.f;

#pragma unroll
                for (int s = 0; s < 16; s++) {
                    unsigned a0 = __float_as_uint(fr[s * 4 + 0]);
                    unsigned a1 = __float_as_uint(fr[s * 4 + 1]);
                    unsigned a2 = __float_as_uint(fr[s * 4 + 2]);
                    unsigned a3 = __float_as_uint(fr[s * 4 + 3]);
#pragma unroll
                    for (int nf = 0; nf < 2; nf++) {
                        const __half* kr = Kb + (wn * 16 + nf * 8 + g) * KP + s * 16 + 2 * t;
                        unsigned b0 = ldsu(kr);
                        unsigned b1 = ldsu(kr + 8);
                        mma_f16(s2[nf], a0, a1, a2, a3, b0, b1);
                    }
                }

                // exp (no max), accumulate sums, store P_j as fp16
                __half* Pb = Ps + (j & 1) * BM * VP;
#pragma unroll
                for (int nf = 0; nf < 2; nf++) {
                    float p0 = __expf(s2[nf][0]), p1 = __expf(s2[nf][1]);
                    float p2 = __expf(s2[nf][2]), p3 = __expf(s2[nf][3]);
                    sum0 += p0 + p1;
                    sum1 += p2 + p3;
                    int r = wm * 16 + g, col = wn * 16 + nf * 8 + 2 * t;
                    *(__half2*)(Pb + r * VP + col)       = __floats2half2_rn(p0, p1);
                    *(__half2*)(Pb + (r + 8) * VP + col) = __floats2half2_rn(p2, p3);
                }

                BAR(1);
                if (j + 2 < NITER) {
                    __half* Kd = Ks + (j & 1) * BN * KP;
                    const __half* Kgs = Kg + (size_t)(j + 2) * BN * DDIM;
#pragma unroll
                    for (int ii = 0; ii < 4; ii++) {
                        int i = lt + ii * 256, r = i >> 5, c = i & 31;
                        cp16(Kd + r * KP + c * 8, Kgs + (size_t)r * DDIM + c * 8);
                    }
                }
                CP_COMMIT();
            }
        } else {
            if (j >= 1) {
                CP_WAIT1();                      // V_{j-1} arrived
                BAR(2);

                const __half* Vb = Vs + ((j - 1) & 1) * 256 * VP;
                const __half* Pb = Ps + ((j - 1) & 1) * BM * VP;
#pragma unroll
                for (int ks = 0; ks < 2; ks++) {
                    unsigned b0r[4], b1r[4];
#pragma unroll
                    for (int nf = 0; nf < 4; nf++) {
                        const __half* vr = Vb + (dw + nf * 8 + g) * VP + ks * 16 + 2 * t;
                        b0r[nf] = ldsu(vr);
                        b1r[nf] = ldsu(vr + 8);
                    }
#pragma unroll
                    for (int mt = 0; mt < 4; mt++) {
                        const __half* pr = Pb + (mt * 16 + g) * VP + ks * 16 + 2 * t;
                        unsigned a0 = ldsu(pr);
                        unsigned a1 = ldsu(pr + 8 * VP);
                        unsigned a2 = ldsu(pr + 8);
                        unsigned a3 = ldsu(pr + 8 * VP + 8);
#pragma unroll
                        for (int nf = 0; nf < 4; nf++)
                            mma_f16(&fr[(mt * 4 + nf) * 4], a0, a1, a2, a3, b0r[nf], b1r[nf]);
                    }
                }

                BAR(2);
                if (j + 1 < NITER) {
                    __half* Vd = Vs + ((j + 1) & 1) * 256 * VP;
                    const __half* Vgs = VgT + (size_t)(j + 1) * BN;
#pragma unroll
                    for (int ii = 0; ii < 4; ii++) {
                        int i = lt + ii * 256, r = i >> 2, c = i & 3;
                        cp16(Vd + r * VP + c * 8, Vgs + (size_t)r * NTOK + c * 8);
                    }
                }
                CP_COMMIT();
            }
        }
    }

    // ---- row-sum reduction (S-half) ----
    if (tid < 256) {
        sum0 += __shfl_xor_sync(0xffffffffu, sum0, 1);
        sum0 += __shfl_xor_sync(0xffffffffu, sum0, 2);
        sum1 += __shfl_xor_sync(0xffffffffu, sum1, 1);
        sum1 += __shfl_xor_sync(0xffffffffu, sum1, 2);
        if (t == 0) {
            row_l2[wn * 64 + wm * 16 + g]     = sum0;
            row_l2[wn * 64 + wm * 16 + 8 + g] = sum1;
        }
    }
    __syncthreads();

    // ---- epilogue: out[b][d][token] = O / l  (PV-half) ----
    if (tid >= 256) {
#pragma unroll
        for (int mt = 0; mt < 4; mt++) {
            int r0 = mt * 16 + g, r1 = r0 + 8;
            float il0 = 1.f / (row_l2[r0] + row_l2[64 + r0]);
            float il1 = 1.f / (row_l2[r1] + row_l2[64 + r1]);
#pragma unroll
            for (int nf = 0; nf < 4; nf++) {
                int d = dw + nf * 8 + 2 * t;
                size_t base = ((size_t)batch * DDIM + d) * NTOK + m0g;
                float* o4 = &fr[(mt * 4 + nf) * 4];
                out[base + r0]        = o4[0] * il0;
                out[base + NTOK + r0] = o4[1] * il0;
                out[base + r1]        = o4[2] * il1;
                out[base + NTOK + r1] = o4[3] * il1;
            }
        }
    }
}

extern "C" void kernel_launch(void* const* d_in, const int* in_sizes, int n_in,
                              void* d_out, int out_size) {
    const float* x  = (const float*)d_in[0];
    const float* Wq = (const float*)d_in[1];
    const float* Wk = (const float*)d_in[2];
    const float* Wv = (const float*)d_in[3];
    float* out = (float*)d_out;

    dim3 gp(NTOK / 128, 12, NBATCH);
    qkv_proj_kernel<<<gp, 256>>>(x, Wq, Wk, Wv);

    cudaFuncSetAttribute(attn_kernel, cudaFuncAttributeMaxDynamicSharedMemorySize,
                         ATTN_SMEM_BYTES);
    dim3 ga(NTOK / BM, NBATCH);
    attn_kernel<<<ga, 512, ATTN_SMEM_BYTES>>>(out);
}

// round 7
// speedup vs baseline: 3.3610x; 1.1407x over previous
#include <cuda_runtime.h>
#include <cuda_fp16.h>
#include <cstdint>

#define NBATCH 8
#define NTOK   4096
#define DDIM   256
#define BM     64
#define BN     64
#define NITER  (NTOK / BN)   // 64
#define KP     264   // Q/K row pitch (halfs): word-bank step 4/row -> conflict-free
#define VP     72    // V row pitch (halfs)
#define PP     72    // P row pitch (halfs)

// fp16 scratch: Q,K token-major [b][tok][d]; V transposed [b][d][tok].
// Q pre-scaled by 1/sqrt(256)=1/16.
__device__ __half g_qh [(size_t)NBATCH * NTOK * DDIM];
__device__ __half g_kh [(size_t)NBATCH * NTOK * DDIM];
__device__ __half g_vTh[(size_t)NBATCH * DDIM * NTOK];

// ---------- helpers ----------
__device__ __forceinline__ unsigned f2tf32(float f) {
    unsigned u; asm("cvt.rna.tf32.f32 %0, %1;" : "=r"(u) : "f"(f)); return u;
}
__device__ __forceinline__ float tf32f(float f) { return __uint_as_float(f2tf32(f)); }

__device__ __forceinline__ unsigned ldsu(const __half* p) {
    return *(const unsigned*)p;
}

__device__ __forceinline__ void mma_f16(float* c, unsigned a0, unsigned a1, unsigned a2,
                                        unsigned a3, unsigned b0, unsigned b1) {
    asm volatile(
        "mma.sync.aligned.m16n8k16.row.col.f32.f16.f16.f32 "
        "{%0,%1,%2,%3},{%4,%5,%6,%7},{%8,%9},{%0,%1,%2,%3};\n"
        : "+f"(c[0]), "+f"(c[1]), "+f"(c[2]), "+f"(c[3])
        : "r"(a0), "r"(a1), "r"(a2), "r"(a3), "r"(b0), "r"(b1));
}

__device__ __forceinline__ void mma_tf32(float* c, unsigned a0, unsigned a1, unsigned a2,
                                         unsigned a3, unsigned b0, unsigned b1) {
    asm volatile(
        "mma.sync.aligned.m16n8k8.row.col.f32.tf32.tf32.f32 "
        "{%0,%1,%2,%3},{%4,%5,%6,%7},{%8,%9},{%0,%1,%2,%3};\n"
        : "+f"(c[0]), "+f"(c[1]), "+f"(c[2]), "+f"(c[3])
        : "r"(a0), "r"(a1), "r"(a2), "r"(a3), "r"(b0), "r"(b1));
}

__device__ __forceinline__ void cp16(void* dst, const void* src) {
    unsigned d = (unsigned)__cvta_generic_to_shared(dst);
    asm volatile("cp.async.cg.shared.global [%0], [%1], 16;" :: "r"(d), "l"(src));
}
#define CP_COMMIT() asm volatile("cp.async.commit_group;" ::: "memory")
#define CP_WAIT1()  asm volatile("cp.async.wait_group 1;" ::: "memory")
#define BAR(id)     asm volatile("bar.sync %0, 256;" :: "r"(id) : "memory")

// ============================================================================
// Kernel 1: FUSED QKV projection — X tile loaded once, 3 accumulator sets.
// CTA: 128 tokens x 64 d-cols x {Q,K,V}. grid: (32, 4, 8).
// ============================================================================
__global__ __launch_bounds__(256) void qkv_proj_kernel(
    const float* __restrict__ x, const float* __restrict__ Wq,
    const float* __restrict__ Wk, const float* __restrict__ Wv)
{
    __shared__ float Xs[32][132];
    __shared__ float Ws[3][64][36];

    const int batch = blockIdx.z;
    const int n0    = blockIdx.x * 128;
    const int d0    = blockIdx.y * 64;

    const int tid = threadIdx.x, warp = tid >> 5, lane = tid & 31;
    const int g = lane >> 2, t = lane & 3;
    const int m0 = warp * 16;

    float acc[3][8][4];
#pragma unroll
    for (int m = 0; m < 3; m++)
#pragma unroll
        for (int nf = 0; nf < 8; nf++)
#pragma unroll
            for (int i = 0; i < 4; i++) acc[m][nf][i] = 0.f;

    for (int kc = 0; kc < 256; kc += 32) {
#pragma unroll
        for (int i = tid; i < 1024; i += 256) {
            int r = i >> 5, cq = i & 31;
            float4 v = *(const float4*)(x + ((size_t)(batch * 256 + kc + r)) * 4096 + n0 + cq * 4);
            float* d = &Xs[r][cq * 4];
            d[0] = tf32f(v.x); d[1] = tf32f(v.y); d[2] = tf32f(v.z); d[3] = tf32f(v.w);
        }
#pragma unroll
        for (int m = 0; m < 3; m++) {
            const float* W = (m == 0) ? Wq : ((m == 1) ? Wk : Wv);
#pragma unroll
            for (int i = tid; i < 512; i += 256) {
                int r = i >> 3, cq = i & 7;
                float4 v = *(const float4*)(W + (size_t)(d0 + r) * 256 + kc + cq * 4);
                float* d = &Ws[m][r][cq * 4];
                d[0] = tf32f(v.x); d[1] = tf32f(v.y); d[2] = tf32f(v.z); d[3] = tf32f(v.w);
            }
        }
        __syncthreads();

#pragma unroll
        for (int k8 = 0; k8 < 32; k8 += 8) {
            unsigned a0 = __float_as_uint(Xs[k8 + t][m0 + g]);
            unsigned a1 = __float_as_uint(Xs[k8 + t][m0 + 8 + g]);
            unsigned a2 = __float_as_uint(Xs[k8 + t + 4][m0 + g]);
            unsigned a3 = __float_as_uint(Xs[k8 + t + 4][m0 + 8 + g]);
#pragma unroll
            for (int m = 0; m < 3; m++)
#pragma unroll
                for (int nf = 0; nf < 8; nf++) {
                    unsigned b0 = __float_as_uint(Ws[m][nf * 8 + g][k8 + t]);
                    unsigned b1 = __float_as_uint(Ws[m][nf * 8 + g][k8 + t + 4]);
                    mma_tf32(acc[m][nf], a0, a1, a2, a3, b0, b1);
                }
        }
        __syncthreads();
    }

    // Q (scaled 1/16) and K: token-major fp16
    {
        __half* qb = g_qh + ((size_t)batch * NTOK + n0 + m0) * DDIM + d0;
        __half* kb = g_kh + ((size_t)batch * NTOK + n0 + m0) * DDIM + d0;
#pragma unroll
        for (int nf = 0; nf < 8; nf++) {
            int d = nf * 8 + 2 * t;
            *(__half2*)(qb + (size_t)g * DDIM + d) =
                __floats2half2_rn(acc[0][nf][0] * 0.0625f, acc[0][nf][1] * 0.0625f);
            *(__half2*)(qb + (size_t)(g + 8) * DDIM + d) =
                __floats2half2_rn(acc[0][nf][2] * 0.0625f, acc[0][nf][3] * 0.0625f);
            *(__half2*)(kb + (size_t)g * DDIM + d) =
                __floats2half2_rn(acc[1][nf][0], acc[1][nf][1]);
            *(__half2*)(kb + (size_t)(g + 8) * DDIM + d) =
                __floats2half2_rn(acc[1][nf][2], acc[1][nf][3]);
        }
    }
    // V transposed: [d][tok]
    {
        __half* vb = g_vTh + (size_t)batch * DDIM * NTOK;
        int tok0 = n0 + m0;
#pragma unroll
        for (int nf = 0; nf < 8; nf++) {
            int d = d0 + nf * 8 + 2 * t;
            vb[(size_t)d * NTOK + tok0 + g]           = __float2half_rn(acc[2][nf][0]);
            vb[(size_t)(d + 1) * NTOK + tok0 + g]     = __float2half_rn(acc[2][nf][1]);
            vb[(size_t)d * NTOK + tok0 + 8 + g]       = __float2half_rn(acc[2][nf][2]);
            vb[(size_t)(d + 1) * NTOK + tok0 + 8 + g] = __float2half_rn(acc[2][nf][3]);
        }
    }
}

// ============================================================================
// Kernel 2: fp16 warp-specialized flash attention, BN=64 (64 iterations).
//   warps 0-7  (S-half):  Q in regs; S_j = Q K_j^T -> exp -> P_j  (16x32 each)
//   warps 8-15 (PV-half): O += P_{j-1} V_{j-1}  (32 d-cols each)
// fr[64]: S-half = Q fragments, PV-half = O accumulators.
// ============================================================================
#define SH_Q   0
#define SH_K   16896                     // 64*264
#define SH_V   (SH_K + 2 * BN * KP)      // +33792 = 50688
#define SH_P   (SH_V + 2 * 256 * VP)     // +36864 = 87552
#define SH_END (SH_P + 2 * BM * PP)      // +9216  = 96768 halfs
#define ATTN_SMEM_BYTES (SH_END * 2 + 128 * 4)

__global__ __launch_bounds__(512) void attn_kernel(float* __restrict__ out)
{
    extern __shared__ __align__(16) __half smh[];
    __half* Qs = smh + SH_Q;
    __half* Ks = smh + SH_K;
    __half* Vs = smh + SH_V;
    __half* Ps = smh + SH_P;
    float* row_l2 = (float*)(smh + SH_END);     // 2 * 64 floats

    const int batch = blockIdx.y;
    const int m0g   = blockIdx.x * BM;
    const int tid = threadIdx.x, warp = tid >> 5, lane = tid & 31;
    const int g = lane >> 2, t = lane & 3;
    const int lt = tid & 255;

    const __half* Qg  = g_qh  + ((size_t)batch * NTOK + m0g) * DDIM;
    const __half* Kg  = g_kh  + (size_t)batch * NTOK * DDIM;
    const __half* VgT = g_vTh + (size_t)batch * DDIM * NTOK;

    // ---- initial cp.async ----
    if (tid < 256) {
        // group 0: Q (64x32 chunks) + K0 (64x32)
#pragma unroll
        for (int ii = 0; ii < 8; ii++) {
            int i = lt + ii * 256, r = i >> 5, c = i & 31;
            cp16(Qs + r * KP + c * 8, Qg + (size_t)r * DDIM + c * 8);
        }
#pragma unroll
        for (int ii = 0; ii < 8; ii++) {
            int i = lt + ii * 256, r = i >> 5, c = i & 31;
            cp16(Ks + r * KP + c * 8, Kg + (size_t)r * DDIM + c * 8);
        }
        CP_COMMIT();
        // group 1: K1
#pragma unroll
        for (int ii = 0; ii < 8; ii++) {
            int i = lt + ii * 256, r = i >> 5, c = i & 31;
            cp16(Ks + BN * KP + r * KP + c * 8, Kg + (size_t)(BN + r) * DDIM + c * 8);
        }
        CP_COMMIT();
    } else {
        // group 0: V0 (256 d-rows x 8 chunks), group 1: V1
#pragma unroll
        for (int ii = 0; ii < 8; ii++) {
            int i = lt + ii * 256, r = i >> 3, c = i & 7;
            cp16(Vs + r * VP + c * 8, VgT + (size_t)r * NTOK + c * 8);
        }
        CP_COMMIT();
#pragma unroll
        for (int ii = 0; ii < 8; ii++) {
            int i = lt + ii * 256, r = i >> 3, c = i & 7;
            cp16(Vs + 256 * VP + r * VP + c * 8, VgT + (size_t)r * NTOK + BN + c * 8);
        }
        CP_COMMIT();
    }

    const int wm = warp >> 1, wn = warp & 1;     // S-half: 4m x 2n -> 16x32 tile
    const int dw = (warp - 8) * 32;              // PV-half d slice
    float sum0 = 0.f, sum1 = 0.f;

    // Union register file: S-half = Q fragments, PV-half = O accumulators.
    float fr[64];
#pragma unroll
    for (int i = 0; i < 64; i++) fr[i] = 0.f;

    for (int j = 0; j <= NITER; j++) {
        __syncthreads();
        if (tid < 256) {
            if (j < NITER) {
                CP_WAIT1();                      // K_j (and Q on j=0) arrived
                BAR(1);

                if (j == 0) {
                    const __half* q0 = Qs + (wm * 16 + g) * KP + 2 * t;
                    const __half* q1 = q0 + 8 * KP;
#pragma unroll
                    for (int s = 0; s < 16; s++) {
                        fr[s * 4 + 0] = __uint_as_float(ldsu(q0 + s * 16));
                        fr[s * 4 + 1] = __uint_as_float(ldsu(q1 + s * 16));
                        fr[s * 4 + 2] = __uint_as_float(ldsu(q0 + s * 16 + 8));
                        fr[s * 4 + 3] = __uint_as_float(ldsu(q1 + s * 16 + 8));
                    }
                }

                const __half* Kb = Ks + (j & 1) * BN * KP;
                float s2[4][4];
#pragma unroll
                for (int nf = 0; nf < 4; nf++)
#pragma unroll
                    for (int i = 0; i < 4; i++) s2[nf][i] = 0.f;

#pragma unroll
                for (int s = 0; s < 16; s++) {
                    unsigned a0 = __float_as_uint(fr[s * 4 + 0]);
                    unsigned a1 = __float_as_uint(fr[s * 4 + 1]);
                    unsigned a2 = __float_as_uint(fr[s * 4 + 2]);
                    unsigned a3 = __float_as_uint(fr[s * 4 + 3]);
#pragma unroll
                    for (int nf = 0; nf < 4; nf++) {
                        const __half* kr = Kb + (wn * 32 + nf * 8 + g) * KP + s * 16 + 2 * t;
                        unsigned b0 = ldsu(kr);
                        unsigned b1 = ldsu(kr + 8);
                        mma_f16(s2[nf], a0, a1, a2, a3, b0, b1);
                    }
                }

                // exp (no max), row-sum accumulation, P store
                __half* Pb = Ps + (j & 1) * BM * PP;
#pragma unroll
                for (int nf = 0; nf < 4; nf++) {
                    float p0 = __expf(s2[nf][0]), p1 = __expf(s2[nf][1]);
                    float p2 = __expf(s2[nf][2]), p3 = __expf(s2[nf][3]);
                    sum0 += p0 + p1;
                    sum1 += p2 + p3;
                    int r = wm * 16 + g, col = wn * 32 + nf * 8 + 2 * t;
                    *(__half2*)(Pb + r * PP + col)       = __floats2half2_rn(p0, p1);
                    *(__half2*)(Pb + (r + 8) * PP + col) = __floats2half2_rn(p2, p3);
                }

                BAR(1);
                if (j + 2 < NITER) {
                    __half* Kd = Ks + (j & 1) * BN * KP;
                    const __half* Kgs = Kg + (size_t)(j + 2) * BN * DDIM;
#pragma unroll
                    for (int ii = 0; ii < 8; ii++) {
                        int i = lt + ii * 256, r = i >> 5, c = i & 31;
                        cp16(Kd + r * KP + c * 8, Kgs + (size_t)r * DDIM + c * 8);
                    }
                }
                CP_COMMIT();
            }
        } else {
            if (j >= 1) {
                CP_WAIT1();                      // V_{j-1} arrived
                BAR(2);

                const __half* Vb = Vs + ((j - 1) & 1) * 256 * VP;
                const __half* Pb = Ps + ((j - 1) & 1) * BM * PP;
#pragma unroll
                for (int ks = 0; ks < 4; ks++) {
                    unsigned b0r[4], b1r[4];
#pragma unroll
                    for (int nf = 0; nf < 4; nf++) {
                        const __half* vr = Vb + (dw + nf * 8 + g) * VP + ks * 16 + 2 * t;
                        b0r[nf] = ldsu(vr);
                        b1r[nf] = ldsu(vr + 8);
                    }
#pragma unroll
                    for (int mt = 0; mt < 4; mt++) {
                        const __half* pr = Pb + (mt * 16 + g) * PP + ks * 16 + 2 * t;
                        unsigned a0 = ldsu(pr);
                        unsigned a1 = ldsu(pr + 8 * PP);
                        unsigned a2 = ldsu(pr + 8);
                        unsigned a3 = ldsu(pr + 8 * PP + 8);
#pragma unroll
                        for (int nf = 0; nf < 4; nf++)
                            mma_f16(&fr[(mt * 4 + nf) * 4], a0, a1, a2, a3, b0r[nf], b1r[nf]);
                    }
                }

                BAR(2);
                if (j + 1 < NITER) {
                    __half* Vd = Vs + ((j + 1) & 1) * 256 * VP;
                    const __half* Vgs = VgT + (size_t)(j + 1) * BN;
#pragma unroll
                    for (int ii = 0; ii < 8; ii++) {
                        int i = lt + ii * 256, r = i >> 3, c = i & 7;
                        cp16(Vd + r * VP + c * 8, Vgs + (size_t)r * NTOK + c * 8);
                    }
                }
                CP_COMMIT();
            }
        }
    }

    // ---- row-sum reduction (S-half) ----
    if (tid < 256) {
        sum0 += __shfl_xor_sync(0xffffffffu, sum0, 1);
        sum0 += __shfl_xor_sync(0xffffffffu, sum0, 2);
        sum1 += __shfl_xor_sync(0xffffffffu, sum1, 1);
        sum1 += __shfl_xor_sync(0xffffffffu, sum1, 2);
        if (t == 0) {
            row_l2[wn * 64 + wm * 16 + g]     = sum0;
            row_l2[wn * 64 + wm * 16 + 8 + g] = sum1;
        }
    }
    __syncthreads();

    // ---- epilogue: out[b][d][token] = O / l  (PV-half) ----
    if (tid >= 256) {
#pragma unroll
        for (int mt = 0; mt < 4; mt++) {
            int r0 = mt * 16 + g, r1 = r0 + 8;
            float il0 = 1.f / (row_l2[r0] + row_l2[64 + r0]);
            float il1 = 1.f / (row_l2[r1] + row_l2[64 + r1]);
#pragma unroll
            for (int nf = 0; nf < 4; nf++) {
                int d = dw + nf * 8 + 2 * t;
                size_t base = ((size_t)batch * DDIM + d) * NTOK + m0g;
                float* o4 = &fr[(mt * 4 + nf) * 4];
                out[base + r0]        = o4[0] * il0;
                out[base + NTOK + r0] = o4[1] * il0;
                out[base + r1]        = o4[2] * il1;
                out[base + NTOK + r1] = o4[3] * il1;
            }
        }
    }
}

extern "C" void kernel_launch(void* const* d_in, const int* in_sizes, int n_in,
                              void* d_out, int out_size) {
    const float* x  = (const float*)d_in[0];
    const float* Wq = (const float*)d_in[1];
    const float* Wk = (const float*)d_in[2];
    const float* Wv = (const float*)d_in[3];
    float* out = (float*)d_out;

    dim3 gp(NTOK / 128, 4, NBATCH);
    qkv_proj_kernel<<<gp, 256>>>(x, Wq, Wk, Wv);

    cudaFuncSetAttribute(attn_kernel, cudaFuncAttributeMaxDynamicSharedMemorySize,
                         ATTN_SMEM_BYTES);
    dim3 ga(NTOK / BM, NBATCH);
    attn_kernel<<<ga, 512, ATTN_SMEM_BYTES>>>(out);
}

// round 11
// speedup vs baseline: 3.4646x; 1.0308x over previous
#include <cuda_runtime.h>
#include <cuda_fp16.h>
#include <cstdint>

#define NBATCH 8
#define NTOK   4096
#define DDIM   256
#define BM     64
#define BN     64
#define NITER  (NTOK / BN)   // 64
#define KP     264   // Q/K row pitch (halfs): row stride 528B = 4 words mod 32 -> LDSM conflict-free
#define VP     72    // V row pitch (halfs): 144B = 4 words mod 32
#define PP     72    // P row pitch (halfs)

// fp16 scratch: Q,K token-major [b][tok][d]; V transposed [b][d][tok].
// Q pre-scaled by 1/sqrt(256)=1/16.
__device__ __half g_qh [(size_t)NBATCH * NTOK * DDIM];
__device__ __half g_kh [(size_t)NBATCH * NTOK * DDIM];
__device__ __half g_vTh[(size_t)NBATCH * DDIM * NTOK];

// ---------- helpers ----------
__device__ __forceinline__ unsigned f2tf32(float f) {
    unsigned u; asm("cvt.rna.tf32.f32 %0, %1;" : "=r"(u) : "f"(f)); return u;
}
__device__ __forceinline__ float tf32f(float f) { return __uint_as_float(f2tf32(f)); }

__device__ __forceinline__ unsigned h2u(__half2 h) {
    union { __half2 h; unsigned u; } cvt;
    cvt.h = h;
    return cvt.u;
}

__device__ __forceinline__ void ldsm4(unsigned& r0, unsigned& r1, unsigned& r2,
                                      unsigned& r3, const __half* p) {
    unsigned a = (unsigned)__cvta_generic_to_shared(p);
    asm volatile("ldmatrix.sync.aligned.m8n8.x4.shared.b16 {%0,%1,%2,%3}, [%4];"
                 : "=r"(r0), "=r"(r1), "=r"(r2), "=r"(r3) : "r"(a));
}
__device__ __forceinline__ void stsm4(__half* p, unsigned r0, unsigned r1,
                                      unsigned r2, unsigned r3) {
    unsigned a = (unsigned)__cvta_generic_to_shared(p);
    asm volatile("stmatrix.sync.aligned.m8n8.x4.shared.b16 [%0], {%1,%2,%3,%4};"
                 :: "r"(a), "r"(r0), "r"(r1), "r"(r2), "r"(r3) : "memory");
}

__device__ __forceinline__ void mma_f16(float* c, unsigned a0, unsigned a1, unsigned a2,
                                        unsigned a3, unsigned b0, unsigned b1) {
    asm volatile(
        "mma.sync.aligned.m16n8k16.row.col.f32.f16.f16.f32 "
        "{%0,%1,%2,%3},{%4,%5,%6,%7},{%8,%9},{%0,%1,%2,%3};\n"
        : "+f"(c[0]), "+f"(c[1]), "+f"(c[2]), "+f"(c[3])
        : "r"(a0), "r"(a1), "r"(a2), "r"(a3), "r"(b0), "r"(b1));
}

__device__ __forceinline__ void mma_tf32(float* c, unsigned a0, unsigned a1, unsigned a2,
                                         unsigned a3, unsigned b0, unsigned b1) {
    asm volatile(
        "mma.sync.aligned.m16n8k8.row.col.f32.tf32.tf32.f32 "
        "{%0,%1,%2,%3},{%4,%5,%6,%7},{%8,%9},{%0,%1,%2,%3};\n"
        : "+f"(c[0]), "+f"(c[1]), "+f"(c[2]), "+f"(c[3])
        : "r"(a0), "r"(a1), "r"(a2), "r"(a3), "r"(b0), "r"(b1));
}

__device__ __forceinline__ void cp16(void* dst, const void* src) {
    unsigned d = (unsigned)__cvta_generic_to_shared(dst);
    asm volatile("cp.async.cg.shared.global [%0], [%1], 16;" :: "r"(d), "l"(src));
}
#define CP_COMMIT() asm volatile("cp.async.commit_group;" ::: "memory")
#define CP_WAIT1()  asm volatile("cp.async.wait_group 1;" ::: "memory")
#define BAR(id)     asm volatile("bar.sync %0, 256;" :: "r"(id) : "memory")

// ============================================================================
// Kernel 1: FUSED QKV projection — X tile loaded once, 3 accumulator sets.
// ============================================================================
__global__ __launch_bounds__(256) void qkv_proj_kernel(
    const float* __restrict__ x, const float* __restrict__ Wq,
    const float* __restrict__ Wk, const float* __restrict__ Wv)
{
    __shared__ float Xs[32][132];
    __shared__ float Ws[3][64][36];

    const int batch = blockIdx.z;
    const int n0    = blockIdx.x * 128;
    const int d0    = blockIdx.y * 64;

    const int tid = threadIdx.x, warp = tid >> 5, lane = tid & 31;
    const int g = lane >> 2, t = lane & 3;
    const int m0 = warp * 16;

    float acc[3][8][4];
#pragma unroll
    for (int m = 0; m < 3; m++)
#pragma unroll
        for (int nf = 0; nf < 8; nf++)
#pragma unroll
            for (int i = 0; i < 4; i++) acc[m][nf][i] = 0.f;

    for (int kc = 0; kc < 256; kc += 32) {
#pragma unroll
        for (int i = tid; i < 1024; i += 256) {
            int r = i >> 5, cq = i & 31;
            float4 v = *(const float4*)(x + ((size_t)(batch * 256 + kc + r)) * 4096 + n0 + cq * 4);
            float* d = &Xs[r][cq * 4];
            d[0] = tf32f(v.x); d[1] = tf32f(v.y); d[2] = tf32f(v.z); d[3] = tf32f(v.w);
        }
#pragma unroll
        for (int m = 0; m < 3; m++) {
            const float* W = (m == 0) ? Wq : ((m == 1) ? Wk : Wv);
#pragma unroll
            for (int i = tid; i < 512; i += 256) {
                int r = i >> 3, cq = i & 7;
                float4 v = *(const float4*)(W + (size_t)(d0 + r) * 256 + kc + cq * 4);
                float* d = &Ws[m][r][cq * 4];
                d[0] = tf32f(v.x); d[1] = tf32f(v.y); d[2] = tf32f(v.z); d[3] = tf32f(v.w);
            }
        }
        __syncthreads();

#pragma unroll
        for (int k8 = 0; k8 < 32; k8 += 8) {
            unsigned a0 = __float_as_uint(Xs[k8 + t][m0 + g]);
            unsigned a1 = __float_as_uint(Xs[k8 + t][m0 + 8 + g]);
            unsigned a2 = __float_as_uint(Xs[k8 + t + 4][m0 + g]);
            unsigned a3 = __float_as_uint(Xs[k8 + t + 4][m0 + 8 + g]);
#pragma unroll
            for (int m = 0; m < 3; m++)
#pragma unroll
                for (int nf = 0; nf < 8; nf++) {
                    unsigned b0 = __float_as_uint(Ws[m][nf * 8 + g][k8 + t]);
                    unsigned b1 = __float_as_uint(Ws[m][nf * 8 + g][k8 + t + 4]);
                    mma_tf32(acc[m][nf], a0, a1, a2, a3, b0, b1);
                }
        }
        __syncthreads();
    }

    {
        __half* qb = g_qh + ((size_t)batch * NTOK + n0 + m0) * DDIM + d0;
        __half* kb = g_kh + ((size_t)batch * NTOK + n0 + m0) * DDIM + d0;
#pragma unroll
        for (int nf = 0; nf < 8; nf++) {
            int d = nf * 8 + 2 * t;
            *(__half2*)(qb + (size_t)g * DDIM + d) =
                __floats2half2_rn(acc[0][nf][0] * 0.0625f, acc[0][nf][1] * 0.0625f);
            *(__half2*)(qb + (size_t)(g + 8) * DDIM + d) =
                __floats2half2_rn(acc[0][nf][2] * 0.0625f, acc[0][nf][3] * 0.0625f);
            *(__half2*)(kb + (size_t)g * DDIM + d) =
                __floats2half2_rn(acc[1][nf][0], acc[1][nf][1]);
            *(__half2*)(kb + (size_t)(g + 8) * DDIM + d) =
                __floats2half2_rn(acc[1][nf][2], acc[1][nf][3]);
        }
    }
    {
        __half* vb = g_vTh + (size_t)batch * DDIM * NTOK;
        int tok0 = n0 + m0;
#pragma unroll
        for (int nf = 0; nf < 8; nf++) {
            int d = d0 + nf * 8 + 2 * t;
            vb[(size_t)d * NTOK + tok0 + g]           = __float2half_rn(acc[2][nf][0]);
            vb[(size_t)(d + 1) * NTOK + tok0 + g]     = __float2half_rn(acc[2][nf][1]);
            vb[(size_t)d * NTOK + tok0 + 8 + g]       = __float2half_rn(acc[2][nf][2]);
            vb[(size_t)(d + 1) * NTOK + tok0 + 8 + g] = __float2half_rn(acc[2][nf][3]);
        }
    }
}

// ============================================================================
// Kernel 2: fp16 warp-specialized flash attention, BN=64, LDSM/STSM fragments.
// ============================================================================
#define SH_Q   0
#define SH_K   16896                     // 64*264
#define SH_V   (SH_K + 2 * BN * KP)      // 50688
#define SH_P   (SH_V + 2 * 256 * VP)     // 87552
#define SH_END (SH_P + 2 * BM * PP)      // 96768 halfs
#define ATTN_SMEM_BYTES (SH_END * 2 + 128 * 4)

__global__ __launch_bounds__(512) void attn_kernel(float* __restrict__ out)
{
    extern __shared__ __align__(16) __half smh[];
    __half* Qs = smh + SH_Q;
    __half* Ks = smh + SH_K;
    __half* Vs = smh + SH_V;
    __half* Ps = smh + SH_P;
    float* row_l2 = (float*)(smh + SH_END);

    const int batch = blockIdx.y;
    const int m0g   = blockIdx.x * BM;
    const int tid = threadIdx.x, warp = tid >> 5, lane = tid & 31;
    const int g = lane >> 2, t = lane & 3;
    const int lt = tid & 255;
    const int lgrp = lane >> 3, lrow = lane & 7;   // ldmatrix lane roles

    const __half* Qg  = g_qh  + ((size_t)batch * NTOK + m0g) * DDIM;
    const __half* Kg  = g_kh  + (size_t)batch * NTOK * DDIM;
    const __half* VgT = g_vTh + (size_t)batch * DDIM * NTOK;

    // ---- initial cp.async ----
    if (tid < 256) {
#pragma unroll
        for (int ii = 0; ii < 8; ii++) {
            int i = lt + ii * 256, r = i >> 5, c = i & 31;
            cp16(Qs + r * KP + c * 8, Qg + (size_t)r * DDIM + c * 8);
        }
#pragma unroll
        for (int ii = 0; ii < 8; ii++) {
            int i = lt + ii * 256, r = i >> 5, c = i & 31;
            cp16(Ks + r * KP + c * 8, Kg + (size_t)r * DDIM + c * 8);
        }
        CP_COMMIT();
#pragma unroll
        for (int ii = 0; ii < 8; ii++) {
            int i = lt + ii * 256, r = i >> 5, c = i & 31;
            cp16(Ks + BN * KP + r * KP + c * 8, Kg + (size_t)(BN + r) * DDIM + c * 8);
        }
        CP_COMMIT();
    } else {
#pragma unroll
        for (int ii = 0; ii < 8; ii++) {
            int i = lt + ii * 256, r = i >> 3, c = i & 7;
            cp16(Vs + r * VP + c * 8, VgT + (size_t)r * NTOK + c * 8);
        }
        CP_COMMIT();
#pragma unroll
        for (int ii = 0; ii < 8; ii++) {
            int i = lt + ii * 256, r = i >> 3, c = i & 7;
            cp16(Vs + 256 * VP + r * VP + c * 8, VgT + (size_t)r * NTOK + BN + c * 8);
        }
        CP_COMMIT();
    }

    const int wm = warp >> 1, wn = warp & 1;     // S-half: 16x32 tiles
    const int dw = (warp - 8) * 32;              // PV-half d slice
    float sum0 = 0.f, sum1 = 0.f;

    // Union register file: S-half = Q fragments, PV-half = O accumulators.
    float fr[64];
#pragma unroll
    for (int i = 0; i < 64; i++) fr[i] = 0.f;

    for (int j = 0; j <= NITER; j++) {
        __syncthreads();
        if (tid < 256) {
            if (j < NITER) {
                CP_WAIT1();
                BAR(1);

                if (j == 0) {
                    // Q A-fragments via LDSM: tiles (rows 0-7/8-15, k 0-7/8-15)
                    const __half* qp = Qs + (wm * 16 + (lgrp & 1) * 8 + lrow) * KP
                                          + (lgrp >> 1) * 8;
#pragma unroll
                    for (int s = 0; s < 16; s++) {
                        unsigned a0, a1, a2, a3;
                        ldsm4(a0, a1, a2, a3, qp + s * 16);
                        fr[s * 4 + 0] = __uint_as_float(a0);
                        fr[s * 4 + 1] = __uint_as_float(a1);
                        fr[s * 4 + 2] = __uint_as_float(a2);
                        fr[s * 4 + 3] = __uint_as_float(a3);
                    }
                }

                const __half* Kb = Ks + (j & 1) * BN * KP;
                // B-fragments: groups = (nf_even k0 | nf_even k8 | nf_odd k0 | nf_odd k8)
                const __half* kp = Kb + (wn * 32 + (lgrp >> 1) * 8 + lrow) * KP
                                      + (lgrp & 1) * 8;

                float s2[4][4];
#pragma unroll
                for (int nf = 0; nf < 4; nf++)
#pragma unroll
                    for (int i = 0; i < 4; i++) s2[nf][i] = 0.f;

#pragma unroll
                for (int s = 0; s < 16; s++) {
                    unsigned a0 = __float_as_uint(fr[s * 4 + 0]);
                    unsigned a1 = __float_as_uint(fr[s * 4 + 1]);
                    unsigned a2 = __float_as_uint(fr[s * 4 + 2]);
                    unsigned a3 = __float_as_uint(fr[s * 4 + 3]);
                    unsigned b0, b1, b2, b3;
                    ldsm4(b0, b1, b2, b3, kp + s * 16);
                    mma_f16(s2[0], a0, a1, a2, a3, b0, b1);
                    mma_f16(s2[1], a0, a1, a2, a3, b2, b3);
                    ldsm4(b0, b1, b2, b3, kp + 16 * KP + s * 16);
                    mma_f16(s2[2], a0, a1, a2, a3, b0, b1);
                    mma_f16(s2[3], a0, a1, a2, a3, b2, b3);
                }

                // exp (no max), row sums, P store via STSM
                __half* Pb = Ps + (j & 1) * BM * PP;
                unsigned up[4], lo[4];
#pragma unroll
                for (int nf = 0; nf < 4; nf++) {
                    float p0 = __expf(s2[nf][0]), p1 = __expf(s2[nf][1]);
                    float p2 = __expf(s2[nf][2]), p3 = __expf(s2[nf][3]);
                    sum0 += p0 + p1;
                    sum1 += p2 + p3;
                    up[nf] = h2u(__floats2half2_rn(p0, p1));
                    lo[nf] = h2u(__floats2half2_rn(p2, p3));
                }
                // tiles: (nf0 up | nf0 lo | nf1 up | nf1 lo) per STSM
                __half* sp = Pb + (wm * 16 + ((lgrp & 1) << 3) + lrow) * PP
                                + wn * 32 + (lgrp >> 1) * 8;
                stsm4(sp,      up[0], lo[0], up[1], lo[1]);
                stsm4(sp + 16, up[2], lo[2], up[3], lo[3]);

                BAR(1);
                if (j + 2 < NITER) {
                    __half* Kd = Ks + (j & 1) * BN * KP;
                    const __half* Kgs = Kg + (size_t)(j + 2) * BN * DDIM;
#pragma unroll
                    for (int ii = 0; ii < 8; ii++) {
                        int i = lt + ii * 256, r = i >> 5, c = i & 31;
                        cp16(Kd + r * KP + c * 8, Kgs + (size_t)r * DDIM + c * 8);
                    }
                }
                CP_COMMIT();
            }
        } else {
            if (j >= 1) {
                CP_WAIT1();
                BAR(2);

                const __half* Vb = Vs + ((j - 1) & 1) * 256 * VP;
                const __half* Pb = Ps + ((j - 1) & 1) * BM * PP;
                // P A-fragment base, V B-fragment base
                const __half* pp = Pb + ((lgrp & 1) * 8 + lrow) * PP + (lgrp >> 1) * 8;
                const __half* vp = Vb + (dw + (lgrp >> 1) * 8 + lrow) * VP + (lgrp & 1) * 8;

#pragma unroll
                for (int ks = 0; ks < 4; ks++) {
                    unsigned b0r[4], b1r[4];
                    ldsm4(b0r[0], b1r[0], b0r[1], b1r[1], vp + ks * 16);
                    ldsm4(b0r[2], b1r[2], b0r[3], b1r[3], vp + 16 * VP + ks * 16);
#pragma unroll
                    for (int mt = 0; mt < 4; mt++) {
                        unsigned a0, a1, a2, a3;
                        ldsm4(a0, a1, a2, a3, pp + mt * 16 * PP + ks * 16);
#pragma unroll
                        for (int nf = 0; nf < 4; nf++)
                            mma_f16(&fr[(mt * 4 + nf) * 4], a0, a1, a2, a3, b0r[nf], b1r[nf]);
                    }
                }

                BAR(2);
                if (j + 1 < NITER) {
                    __half* Vd = Vs + ((j + 1) & 1) * 256 * VP;
                    const __half* Vgs = VgT + (size_t)(j + 1) * BN;
#pragma unroll
                    for (int ii = 0; ii < 8; ii++) {
                        int i = lt + ii * 256, r = i >> 3, c = i & 7;
                        cp16(Vd + r * VP + c * 8, Vgs + (size_t)r * NTOK + c * 8);
                    }
                }
                CP_COMMIT();
            }
        }
    }

    // ---- row-sum reduction (S-half) ----
    if (tid < 256) {
        sum0 += __shfl_xor_sync(0xffffffffu, sum0, 1);
        sum0 += __shfl_xor_sync(0xffffffffu, sum0, 2);
        sum1 += __shfl_xor_sync(0xffffffffu, sum1, 1);
        sum1 += __shfl_xor_sync(0xffffffffu, sum1, 2);
        if (t == 0) {
            row_l2[wn * 64 + wm * 16 + g]     = sum0;
            row_l2[wn * 64 + wm * 16 + 8 + g] = sum1;
        }
    }
    __syncthreads();

    // ---- epilogue: out[b][d][token] = O / l  (PV-half) ----
    if (tid >= 256) {
#pragma unroll
        for (int mt = 0; mt < 4; mt++) {
            int r0 = mt * 16 + g, r1 = r0 + 8;
            float il0 = 1.f / (row_l2[r0] + row_l2[64 + r0]);
            float il1 = 1.f / (row_l2[r1] + row_l2[64 + r1]);
#pragma unroll
            for (int nf = 0; nf < 4; nf++) {
                int d = dw + nf * 8 + 2 * t;
                size_t base = ((size_t)batch * DDIM + d) * NTOK + m0g;
                float* o4 = &fr[(mt * 4 + nf) * 4];
                out[base + r0]        = o4[0] * il0;
                out[base + NTOK + r0] = o4[1] * il0;
                out[base + r1]        = o4[2] * il1;
                out[base + NTOK + r1] = o4[3] * il1;
            }
        }
    }
}

extern "C" void kernel_launch(void* const* d_in, const int* in_sizes, int n_in,
                              void* d_out, int out_size) {
    const float* x  = (const float*)d_in[0];
    const float* Wq = (const float*)d_in[1];
    const float* Wk = (const float*)d_in[2];
    const float* Wv = (const float*)d_in[3];
    float* out = (float*)d_out;

    dim3 gp(NTOK / 128, 4, NBATCH);
    qkv_proj_kernel<<<gp, 256>>>(x, Wq, Wk, Wv);

    cudaFuncSetAttribute(attn_kernel, cudaFuncAttributeMaxDynamicSharedMemorySize,
                         ATTN_SMEM_BYTES);
    dim3 ga(NTOK / BM, NBATCH);
    attn_kernel<<<ga, 512, ATTN_SMEM_BYTES>>>(out);
}

// round 14
// speedup vs baseline: 3.8377x; 1.1077x over previous
#include <cuda_runtime.h>
#include <cuda_fp16.h>
#include <cstdint>

#define NBATCH 8
#define NTOK   4096
#define DDIM   256
#define BM     64
#define BN     64
#define NITER  (NTOK / BN)   // 64
#define KP     264   // Q/K row pitch (halfs)
#define VP     72    // V row pitch (halfs)
#define PP     72    // P row pitch (halfs)

// fp16 scratch: Q,K token-major [b][tok][d]; V transposed [b][d][tok].
// Q pre-scaled by 1/sqrt(256)=1/16.
__device__ __half g_qh [(size_t)NBATCH * NTOK * DDIM];
__device__ __half g_kh [(size_t)NBATCH * NTOK * DDIM];
__device__ __half g_vTh[(size_t)NBATCH * DDIM * NTOK];

// ---------- helpers ----------
__device__ __forceinline__ unsigned f2tf32(float f) {
    unsigned u; asm("cvt.rna.tf32.f32 %0, %1;" : "=r"(u) : "f"(f)); return u;
}
__device__ __forceinline__ float tf32f(float f) { return __uint_as_float(f2tf32(f)); }

__device__ __forceinline__ unsigned h2u(__half2 h) {
    union { __half2 h; unsigned u; } cvt;
    cvt.h = h;
    return cvt.u;
}

__device__ __forceinline__ void ldsm4(unsigned& r0, unsigned& r1, unsigned& r2,
                                      unsigned& r3, const __half* p) {
    unsigned a = (unsigned)__cvta_generic_to_shared(p);
    asm volatile("ldmatrix.sync.aligned.m8n8.x4.shared.b16 {%0,%1,%2,%3}, [%4];"
                 : "=r"(r0), "=r"(r1), "=r"(r2), "=r"(r3) : "r"(a));
}
__device__ __forceinline__ void stsm4(__half* p, unsigned r0, unsigned r1,
                                      unsigned r2, unsigned r3) {
    unsigned a = (unsigned)__cvta_generic_to_shared(p);
    asm volatile("stmatrix.sync.aligned.m8n8.x4.shared.b16 [%0], {%1,%2,%3,%4};"
                 :: "r"(a), "r"(r0), "r"(r1), "r"(r2), "r"(r3) : "memory");
}

__device__ __forceinline__ void mma_f16(float* c, unsigned a0, unsigned a1, unsigned a2,
                                        unsigned a3, unsigned b0, unsigned b1) {
    asm volatile(
        "mma.sync.aligned.m16n8k16.row.col.f32.f16.f16.f32 "
        "{%0,%1,%2,%3},{%4,%5,%6,%7},{%8,%9},{%0,%1,%2,%3};\n"
        : "+f"(c[0]), "+f"(c[1]), "+f"(c[2]), "+f"(c[3])
        : "r"(a0), "r"(a1), "r"(a2), "r"(a3), "r"(b0), "r"(b1));
}

__device__ __forceinline__ void mma_tf32(float* c, unsigned a0, unsigned a1, unsigned a2,
                                         unsigned a3, unsigned b0, unsigned b1) {
    asm volatile(
        "mma.sync.aligned.m16n8k8.row.col.f32.tf32.tf32.f32 "
        "{%0,%1,%2,%3},{%4,%5,%6,%7},{%8,%9},{%0,%1,%2,%3};\n"
        : "+f"(c[0]), "+f"(c[1]), "+f"(c[2]), "+f"(c[3])
        : "r"(a0), "r"(a1), "r"(a2), "r"(a3), "r"(b0), "r"(b1));
}

__device__ __forceinline__ void cp16(void* dst, const void* src) {
    unsigned d = (unsigned)__cvta_generic_to_shared(dst);
    asm volatile("cp.async.cg.shared.global [%0], [%1], 16;" :: "r"(d), "l"(src));
}
#define CP_COMMIT() asm volatile("cp.async.commit_group;" ::: "memory")
#define CP_WAIT1()  asm volatile("cp.async.wait_group 1;" ::: "memory")
#define BAR(id)      asm volatile("bar.sync %0, 256;"   :: "r"(id) : "memory")
#define BAR_ARR(id)  asm volatile("bar.arrive %0, 512;" :: "r"(id) : "memory")
#define BAR_WAIT(id) asm volatile("bar.sync %0, 512;"   :: "r"(id) : "memory")

// ============================================================================
// Kernel 1: FUSED QKV projection — X tile loaded once, 3 accumulator sets.
// ============================================================================
__global__ __launch_bounds__(256) void qkv_proj_kernel(
    const float* __restrict__ x, const float* __restrict__ Wq,
    const float* __restrict__ Wk, const float* __restrict__ Wv)
{
    __shared__ float Xs[32][132];
    __shared__ float Ws[3][64][36];

    const int batch = blockIdx.z;
    const int n0    = blockIdx.x * 128;
    const int d0    = blockIdx.y * 64;

    const int tid = threadIdx.x, warp = tid >> 5, lane = tid & 31;
    const int g = lane >> 2, t = lane & 3;
    const int m0 = warp * 16;

    float acc[3][8][4];
#pragma unroll
    for (int m = 0; m < 3; m++)
#pragma unroll
        for (int nf = 0; nf < 8; nf++)
#pragma unroll
            for (int i = 0; i < 4; i++) acc[m][nf][i] = 0.f;

    for (int kc = 0; kc < 256; kc += 32) {
#pragma unroll
        for (int i = tid; i < 1024; i += 256) {
            int r = i >> 5, cq = i & 31;
            float4 v = *(const float4*)(x + ((size_t)(batch * 256 + kc + r)) * 4096 + n0 + cq * 4);
            float* d = &Xs[r][cq * 4];
            d[0] = tf32f(v.x); d[1] = tf32f(v.y); d[2] = tf32f(v.z); d[3] = tf32f(v.w);
        }
#pragma unroll
        for (int m = 0; m < 3; m++) {
            const float* W = (m == 0) ? Wq : ((m == 1) ? Wk : Wv);
#pragma unroll
            for (int i = tid; i < 512; i += 256) {
                int r = i >> 3, cq = i & 7;
                float4 v = *(const float4*)(W + (size_t)(d0 + r) * 256 + kc + cq * 4);
                float* d = &Ws[m][r][cq * 4];
                d[0] = tf32f(v.x); d[1] = tf32f(v.y); d[2] = tf32f(v.z); d[3] = tf32f(v.w);
            }
        }
        __syncthreads();

#pragma unroll
        for (int k8 = 0; k8 < 32; k8 += 8) {
            unsigned a0 = __float_as_uint(Xs[k8 + t][m0 + g]);
            unsigned a1 = __float_as_uint(Xs[k8 + t][m0 + 8 + g]);
            unsigned a2 = __float_as_uint(Xs[k8 + t + 4][m0 + g]);
            unsigned a3 = __float_as_uint(Xs[k8 + t + 4][m0 + 8 + g]);
#pragma unroll
            for (int m = 0; m < 3; m++)
#pragma unroll
                for (int nf = 0; nf < 8; nf++) {
                    unsigned b0 = __float_as_uint(Ws[m][nf * 8 + g][k8 + t]);
                    unsigned b1 = __float_as_uint(Ws[m][nf * 8 + g][k8 + t + 4]);
                    mma_tf32(acc[m][nf], a0, a1, a2, a3, b0, b1);
                }
        }
        __syncthreads();
    }

    {
        __half* qb = g_qh + ((size_t)batch * NTOK + n0 + m0) * DDIM + d0;
        __half* kb = g_kh + ((size_t)batch * NTOK + n0 + m0) * DDIM + d0;
#pragma unroll
        for (int nf = 0; nf < 8; nf++) {
            int d = nf * 8 + 2 * t;
            *(__half2*)(qb + (size_t)g * DDIM + d) =
                __floats2half2_rn(acc[0][nf][0] * 0.0625f, acc[0][nf][1] * 0.0625f);
            *(__half2*)(qb + (size_t)(g + 8) * DDIM + d) =
                __floats2half2_rn(acc[0][nf][2] * 0.0625f, acc[0][nf][3] * 0.0625f);
            *(__half2*)(kb + (size_t)g * DDIM + d) =
                __floats2half2_rn(acc[1][nf][0], acc[1][nf][1]);
            *(__half2*)(kb + (size_t)(g + 8) * DDIM + d) =
                __floats2half2_rn(acc[1][nf][2], acc[1][nf][3]);
        }
    }
    {
        __half* vb = g_vTh + (size_t)batch * DDIM * NTOK;
        int tok0 = n0 + m0;
#pragma unroll
        for (int nf = 0; nf < 8; nf++) {
            int d = d0 + nf * 8 + 2 * t;
            vb[(size_t)d * NTOK + tok0 + g]           = __float2half_rn(acc[2][nf][0]);
            vb[(size_t)(d + 1) * NTOK + tok0 + g]     = __float2half_rn(acc[2][nf][1]);
            vb[(size_t)d * NTOK + tok0 + 8 + g]       = __float2half_rn(acc[2][nf][2]);
            vb[(size_t)(d + 1) * NTOK + tok0 + 8 + g] = __float2half_rn(acc[2][nf][3]);
        }
    }
}

// ============================================================================
// Kernel 2: decoupled warp-specialized flash attention, lag-2, 4 P buffers,
// PER-SLOT named barriers (full[s]=3+s, empty[s]=7+s, s=iter&3).
// Each barrier trips with exactly one 256-arrive + one 256-sync batch —
// no trip-without-waiter is possible (orphan batch = 256 < 512).
//   warps 0-7  (S-half):  wait empty[j&3] (j>=4); S_j -> exp -> P_j; arrive full[j&3]
//   warps 8-15 (PV-half): wait full[i0&3]; O += P_{i0} V_{i0}; arrive empty[i0&3]
// ============================================================================
#define SH_Q   0
#define SH_K   16896                     // 64*264
#define SH_V   (SH_K + 2 * BN * KP)      // 50688
#define SH_P   (SH_V + 2 * 256 * VP)     // 87552
#define SH_END (SH_P + 4 * BM * PP)      // 105984 halfs
#define ATTN_SMEM_BYTES (SH_END * 2 + 128 * 4)

__global__ __launch_bounds__(512) void attn_kernel(float* __restrict__ out)
{
    extern __shared__ __align__(16) __half smh[];
    __half* Qs = smh + SH_Q;
    __half* Ks = smh + SH_K;
    __half* Vs = smh + SH_V;
    __half* Ps = smh + SH_P;
    float* row_l2 = (float*)(smh + SH_END);

    const int batch = blockIdx.y;
    const int m0g   = blockIdx.x * BM;
    const int tid = threadIdx.x, warp = tid >> 5, lane = tid & 31;
    const int g = lane >> 2, t = lane & 3;
    const int lt = tid & 255;
    const int lgrp = lane >> 3, lrow = lane & 7;

    const __half* Qg  = g_qh  + ((size_t)batch * NTOK + m0g) * DDIM;
    const __half* Kg  = g_kh  + (size_t)batch * NTOK * DDIM;
    const __half* VgT = g_vTh + (size_t)batch * DDIM * NTOK;

    // ---- initial cp.async ----
    if (tid < 256) {
#pragma unroll
        for (int ii = 0; ii < 8; ii++) {
            int i = lt + ii * 256, r = i >> 5, c = i & 31;
            cp16(Qs + r * KP + c * 8, Qg + (size_t)r * DDIM + c * 8);
        }
#pragma unroll
        for (int ii = 0; ii < 8; ii++) {
            int i = lt + ii * 256, r = i >> 5, c = i & 31;
            cp16(Ks + r * KP + c * 8, Kg + (size_t)r * DDIM + c * 8);
        }
        CP_COMMIT();
#pragma unroll
        for (int ii = 0; ii < 8; ii++) {
            int i = lt + ii * 256, r = i >> 5, c = i & 31;
            cp16(Ks + BN * KP + r * KP + c * 8, Kg + (size_t)(BN + r) * DDIM + c * 8);
        }
        CP_COMMIT();
    } else {
#pragma unroll
        for (int ii = 0; ii < 8; ii++) {
            int i = lt + ii * 256, r = i >> 3, c = i & 7;
            cp16(Vs + r * VP + c * 8, VgT + (size_t)r * NTOK + c * 8);
        }
        CP_COMMIT();
#pragma unroll
        for (int ii = 0; ii < 8; ii++) {
            int i = lt + ii * 256, r = i >> 3, c = i & 7;
            cp16(Vs + 256 * VP + r * VP + c * 8, VgT + (size_t)r * NTOK + BN + c * 8);
        }
        CP_COMMIT();
    }

    const int wm = warp >> 1, wn = warp & 1;     // S-half: 16x32 tiles
    const int dw = (warp - 8) * 32;              // PV-half d slice
    float sum0 = 0.f, sum1 = 0.f;

    // Union register file: S-half = Q fragments, PV-half = O accumulators.
    float fr[64];
#pragma unroll
    for (int i = 0; i < 64; i++) fr[i] = 0.f;

    // S active for j in [0,NITER); PV active for j in [2,NITER+2), i0 = j-2.
    for (int j = 0; j < NITER + 2; j++) {
        if (tid < 256) {
            if (j < NITER) {
                if (j >= 4) BAR_WAIT(7 + (j & 3));   // P buf (j&3) freed by PV @ i0=j-4
                CP_WAIT1();                           // K_j (and Q on j=0) arrived
                BAR(1);

                if (j == 0) {
                    const __half* qp = Qs + (wm * 16 + (lgrp & 1) * 8 + lrow) * KP
                                          + (lgrp >> 1) * 8;
#pragma unroll
                    for (int s = 0; s < 16; s++) {
                        unsigned a0, a1, a2, a3;
                        ldsm4(a0, a1, a2, a3, qp + s * 16);
                        fr[s * 4 + 0] = __uint_as_float(a0);
                        fr[s * 4 + 1] = __uint_as_float(a1);
                        fr[s * 4 + 2] = __uint_as_float(a2);
                        fr[s * 4 + 3] = __uint_as_float(a3);
                    }
                }

                const __half* Kb = Ks + (j & 1) * BN * KP;
                const __half* kp = Kb + (wn * 32 + (lgrp >> 1) * 8 + lrow) * KP
                                      + (lgrp & 1) * 8;

                float s2[4][4];
#pragma unroll
                for (int nf = 0; nf < 4; nf++)
#pragma unroll
                    for (int i = 0; i < 4; i++) s2[nf][i] = 0.f;

#pragma unroll
                for (int s = 0; s < 16; s++) {
                    unsigned a0 = __float_as_uint(fr[s * 4 + 0]);
                    unsigned a1 = __float_as_uint(fr[s * 4 + 1]);
                    unsigned a2 = __float_as_uint(fr[s * 4 + 2]);
                    unsigned a3 = __float_as_uint(fr[s * 4 + 3]);
                    unsigned b0, b1, b2, b3;
                    ldsm4(b0, b1, b2, b3, kp + s * 16);
                    mma_f16(s2[0], a0, a1, a2, a3, b0, b1);
                    mma_f16(s2[1], a0, a1, a2, a3, b2, b3);
                    ldsm4(b0, b1, b2, b3, kp + 16 * KP + s * 16);
                    mma_f16(s2[2], a0, a1, a2, a3, b0, b1);
                    mma_f16(s2[3], a0, a1, a2, a3, b2, b3);
                }

                // exp (no max), row sums, P store via STSM into buf j&3
                __half* Pb = Ps + (j & 3) * BM * PP;
                unsigned up[4], lo[4];
#pragma unroll
                for (int nf = 0; nf < 4; nf++) {
                    float p0 = __expf(s2[nf][0]), p1 = __expf(s2[nf][1]);
                    float p2 = __expf(s2[nf][2]), p3 = __expf(s2[nf][3]);
                    sum0 += p0 + p1;
                    sum1 += p2 + p3;
                    up[nf] = h2u(__floats2half2_rn(p0, p1));
                    lo[nf] = h2u(__floats2half2_rn(p2, p3));
                }
                __half* sp = Pb + (wm * 16 + ((lgrp & 1) << 3) + lrow) * PP
                                + wn * 32 + (lgrp >> 1) * 8;
                stsm4(sp,      up[0], lo[0], up[1], lo[1]);
                stsm4(sp + 16, up[2], lo[2], up[3], lo[3]);

                BAR_ARR(3 + (j & 3));                 // P_j published

                BAR(1);                               // S-half done with K buf j&1
                if (j + 2 < NITER) {
                    __half* Kd = Ks + (j & 1) * BN * KP;
                    const __half* Kgs = Kg + (size_t)(j + 2) * BN * DDIM;
#pragma unroll
                    for (int ii = 0; ii < 8; ii++) {
                        int i = lt + ii * 256, r = i >> 5, c = i & 31;
                        cp16(Kd + r * KP + c * 8, Kgs + (size_t)r * DDIM + c * 8);
                    }
                }
                CP_COMMIT();
            }
        } else {
            if (j >= 2) {
                const int i0 = j - 2;                 // tile being consumed
                CP_WAIT1();                           // V_{i0} arrived
                BAR(2);
                BAR_WAIT(3 + (i0 & 3));               // P_{i0} published

                const __half* Vb = Vs + (i0 & 1) * 256 * VP;
                const __half* Pb = Ps + (i0 & 3) * BM * PP;
                const __half* pp = Pb + ((lgrp & 1) * 8 + lrow) * PP + (lgrp >> 1) * 8;
                const __half* vp = Vb + (dw + (lgrp >> 1) * 8 + lrow) * VP + (lgrp & 1) * 8;

#pragma unroll
                for (int ks = 0; ks < 4; ks++) {
                    unsigned b0r[4], b1r[4];
                    ldsm4(b0r[0], b1r[0], b0r[1], b1r[1], vp + ks * 16);
                    ldsm4(b0r[2], b1r[2], b0r[3], b1r[3], vp + 16 * VP + ks * 16);
#pragma unroll
                    for (int mt = 0; mt < 4; mt++) {
                        unsigned a0, a1, a2, a3;
                        ldsm4(a0, a1, a2, a3, pp + mt * 16 * PP + ks * 16);
#pragma unroll
                        for (int nf = 0; nf < 4; nf++)
                            mma_f16(&fr[(mt * 4 + nf) * 4], a0, a1, a2, a3, b0r[nf], b1r[nf]);
                    }
                }

                BAR_ARR(7 + (i0 & 3));                // P buf (i0&3) free

                BAR(2);                               // PV-half done with V buf i0&1
                if (i0 + 2 < NITER) {
                    __half* Vd = Vs + (i0 & 1) * 256 * VP;
                    const __half* Vgs = VgT + (size_t)(i0 + 2) * BN;
#pragma unroll
                    for (int ii = 0; ii < 8; ii++) {
                        int ix = lt + ii * 256, r = ix >> 3, c = ix & 7;
                        cp16(Vd + r * VP + c * 8, Vgs + (size_t)r * NTOK + c * 8);
                    }
                }
                CP_COMMIT();
            }
        }
    }

    // ---- row-sum reduction (S-half) ----
    if (tid < 256) {
        sum0 += __shfl_xor_sync(0xffffffffu, sum0, 1);
        sum0 += __shfl_xor_sync(0xffffffffu, sum0, 2);
        sum1 += __shfl_xor_sync(0xffffffffu, sum1, 1);
        sum1 += __shfl_xor_sync(0xffffffffu, sum1, 2);
        if (t == 0) {
            row_l2[wn * 64 + wm * 16 + g]     = sum0;
            row_l2[wn * 64 + wm * 16 + 8 + g] = sum1;
        }
    }
    __syncthreads();

    // ---- epilogue: out[b][d][token] = O / l  (PV-half) ----
    if (tid >= 256) {
#pragma unroll
        for (int mt = 0; mt < 4; mt++) {
            int r0 = mt * 16 + g, r1 = r0 + 8;
            float il0 = 1.f / (row_l2[r0] + row_l2[64 + r0]);
            float il1 = 1.f / (row_l2[r1] + row_l2[64 + r1]);
#pragma unroll
            for (int nf = 0; nf < 4; nf++) {
                int d = dw + nf * 8 + 2 * t;
                size_t base = ((size_t)batch * DDIM + d) * NTOK + m0g;
                float* o4 = &fr[(mt * 4 + nf) * 4];
                out[base + r0]        = o4[0] * il0;
                out[base + NTOK + r0] = o4[1] * il0;
                out[base + r1]        = o4[2] * il1;
                out[base + NTOK + r1] = o4[3] * il1;
            }
        }
    }
}

extern "C" void kernel_launch(void* const* d_in, const int* in_sizes, int n_in,
                              void* d_out, int out_size) {
    const float* x  = (const float*)d_in[0];
    const float* Wq = (const float*)d_in[1];
    const float* Wk = (const float*)d_in[2];
    const float* Wv = (const float*)d_in[3];
    float* out = (float*)d_out;

    dim3 gp(NTOK / 128, 4, NBATCH);
    qkv_proj_kernel<<<gp, 256>>>(x, Wq, Wk, Wv);

    cudaFuncSetAttribute(attn_kernel, cudaFuncAttributeMaxDynamicSharedMemorySize,
                         ATTN_SMEM_BYTES);
    dim3 ga(NTOK / BM, NBATCH);
    attn_kernel<<<ga, 512, ATTN_SMEM_BYTES>>>(out);
}